// round 1
// baseline (speedup 1.0000x reference)
#include <cuda_runtime.h>
#include <math.h>
#include <stdint.h>

#define BB 16
#define NN 196
#define DD 512
#define MM 20
#define HH 8
#define HD 64
#define RTOT (BB*NN)   /* 3136 */

// ---------------- scratch (device globals; no allocation) ----------------
__device__ float g_qkv[RTOT*3*DD];   // [r][1536]
__device__ float g_att[RTOT*DD];     // attention output (pre out-proj)
__device__ float g_enh[RTOT*DD];     // F_enh
__device__ float g_h[RTOT*DD];       // after w1 (pre-LN)
__device__ float g_qp[RTOT*MM];      // Qp

// ---------------- helpers ----------------
__device__ __forceinline__ float warp_sum(float v){
#pragma unroll
    for (int off=16; off; off>>=1) v += __shfl_xor_sync(0xffffffffu, v, off);
    return v;
}
__device__ __forceinline__ float warp_max(float v){
#pragma unroll
    for (int off=16; off; off>>=1) v = fmaxf(v, __shfl_xor_sync(0xffffffffu, v, off));
    return v;
}

// ---------------- GEMM: C[r][o] = sum_k A[r][k]*W[o][k] + bias[o] (+res) ----
// BM=64, BN=128, BK=16, 256 threads, 4x8 microtile.
template<bool RES>
__global__ void __launch_bounds__(256) gemm_nt(
    const float* __restrict__ A, const float* __restrict__ W,
    const float* __restrict__ bias, const float* __restrict__ res,
    float* __restrict__ C, int K, int O)
{
    __shared__ __align__(16) float As[16*68];
    __shared__ __align__(16) float Bs[16*132];
    const int tid = threadIdx.x;
    const int rb = blockIdx.y*64, ob = blockIdx.x*128;
    const int tx = tid & 15, ty = tid >> 4;

    float acc[4][8];
#pragma unroll
    for (int i=0;i<4;i++)
#pragma unroll
        for (int j=0;j<8;j++) acc[i][j]=0.f;

    for (int k0=0;k0<K;k0+=16){
#pragma unroll
        for (int i=0;i<4;i++){
            int idx = tid + i*256; int row = idx>>4, col = idx&15;
            As[col*68+row] = A[(size_t)(rb+row)*K + k0+col];
        }
#pragma unroll
        for (int i=0;i<8;i++){
            int idx = tid + i*256; int row = idx>>4, col = idx&15;
            Bs[col*132+row] = W[(size_t)(ob+row)*K + k0+col];
        }
        __syncthreads();
#pragma unroll
        for (int kk=0;kk<16;kk++){
            float4 av  = *(const float4*)&As[kk*68 + ty*4];
            float4 bv0 = *(const float4*)&Bs[kk*132 + tx*8];
            float4 bv1 = *(const float4*)&Bs[kk*132 + tx*8 + 4];
            float a[4] = {av.x, av.y, av.z, av.w};
            float b[8] = {bv0.x,bv0.y,bv0.z,bv0.w, bv1.x,bv1.y,bv1.z,bv1.w};
#pragma unroll
            for (int i=0;i<4;i++)
#pragma unroll
                for (int j=0;j<8;j++) acc[i][j] += a[i]*b[j];
        }
        __syncthreads();
    }
#pragma unroll
    for (int i=0;i<4;i++){
        int r = rb + ty*4 + i;
#pragma unroll
        for (int j=0;j<8;j++){
            int o = ob + tx*8 + j;
            float v = acc[i][j] + bias[o];
            if (RES) v += res[(size_t)r*O + o];
            C[(size_t)r*O + o] = v;
        }
    }
}

// ---------------- attention: block per (qchunk, head, batch) ----------------
// 28 query rows per block, streaming softmax over 4 tiles of 49 keys.
__global__ void __launch_bounds__(256) attn_kernel()
{
    const int qc = blockIdx.x, h = blockIdx.y, b = blockIdx.z;
    const int r0 = qc*28;
    __shared__ __align__(16) float Qs[28*68];
    __shared__ __align__(16) float Ks[49*68];
    __shared__ __align__(16) float Vs[49*68];
    __shared__ float S[28*52];
    const int tid = threadIdx.x, lane = tid & 31, w = tid >> 5;

    for (int idx=tid; idx<28*64; idx+=256){
        int row = idx>>6, kx = idx&63;
        Qs[row*68+kx] = g_qkv[(size_t)(b*NN + r0+row)*1536 + h*64 + kx];
    }

    const int nrows = (w<4)?4:3;
    float mrun[4], lrun[4], o0[4], o1[4];
#pragma unroll
    for (int rr=0; rr<4; rr++){ mrun[rr]=-1e30f; lrun[rr]=0.f; o0[rr]=0.f; o1[rr]=0.f; }

    for (int t=0;t<4;t++){
        if (t>0) __syncthreads();            // previous row-phase done before overwrite
        for (int idx=tid; idx<49*64; idx+=256){
            int j = idx>>6, kx = idx&63;
            int nk = t*49 + j;
            size_t base = (size_t)(b*NN + nk)*1536 + h*64 + kx;
            Ks[j*68+kx] = g_qkv[base + 512];
            Vs[j*68+kx] = g_qkv[base + 1024];
        }
        __syncthreads();
        // scores
        for (int i=tid; i<28*49; i+=256){
            int row = i/49, j = i - row*49;
            const float4* q4 = (const float4*)&Qs[row*68];
            const float4* k4 = (const float4*)&Ks[j*68];
            float acc = 0.f;
#pragma unroll
            for (int kx=0; kx<16; kx++){
                float4 qa = q4[kx], ka = k4[kx];
                acc += qa.x*ka.x + qa.y*ka.y + qa.z*ka.z + qa.w*ka.w;
            }
            S[row*52+j] = acc * 0.125f;
        }
        __syncthreads();
        // row phase: warp w owns rows w, w+8, w+16, (w+24)
        for (int rr=0; rr<nrows; rr++){
            int row = w + 8*rr;
            float s0 = (lane<49) ? S[row*52+lane]    : -1e30f;
            float s1 = (lane<17) ? S[row*52+lane+32] : -1e30f;
            float tm = warp_max(fmaxf(s0,s1));
            float mnew = fmaxf(mrun[rr], tm);
            float alpha = __expf(mrun[rr]-mnew);
            float p0 = (lane<49) ? __expf(s0-mnew) : 0.f;
            float p1 = (lane<17) ? __expf(s1-mnew) : 0.f;
            float psum = warp_sum(p0+p1);
            lrun[rr] = lrun[rr]*alpha + psum;
            mrun[rr] = mnew;
            if (lane<49) S[row*52+lane]    = p0;
            if (lane<17) S[row*52+lane+32] = p1;
            __syncwarp();
            float a0 = o0[rr]*alpha, a1 = o1[rr]*alpha;
#pragma unroll 7
            for (int j=0;j<49;j++){
                float pj = S[row*52+j];
                a0 += pj * Vs[j*68+lane];
                a1 += pj * Vs[j*68+lane+32];
            }
            o0[rr]=a0; o1[rr]=a1;
        }
    }
    for (int rr=0; rr<nrows; rr++){
        int row = w + 8*rr;
        float inv = 1.f/lrun[rr];
        size_t base = (size_t)(b*NN + r0+row)*512 + h*64;
        g_att[base+lane]    = o0[rr]*inv;
        g_att[base+lane+32] = o1[rr]*inv;
    }
}

// ---------------- LayerNorm + GELU(exact) + w2 -> Qp ----------------
__global__ void __launch_bounds__(256) ln_gelu_qp(
    const float* __restrict__ hin, const float* __restrict__ lng,
    const float* __restrict__ lnb, const float* __restrict__ w2,
    const float* __restrict__ b2, float* __restrict__ qp)
{
    const int r = blockIdx.x, tid = threadIdx.x, lane = tid&31, w = tid>>5;
    __shared__ float gs[512];
    __shared__ float red[16];
    float x0 = hin[(size_t)r*512 + tid];
    float x1 = hin[(size_t)r*512 + tid + 256];
    float s  = warp_sum(x0 + x1);
    float sq = warp_sum(x0*x0 + x1*x1);
    if (lane==0){ red[w]=s; red[w+8]=sq; }
    __syncthreads();
    if (tid==0){
        float S=0,Q=0;
#pragma unroll
        for (int i=0;i<8;i++){ S+=red[i]; Q+=red[i+8]; }
        red[0]=S; red[1]=Q;
    }
    __syncthreads();
    float mean = red[0]*(1.f/512.f);
    float var  = red[1]*(1.f/512.f) - mean*mean;
    float rstd = rsqrtf(var + 1e-5f);

    {
        float y0 = (x0-mean)*rstd*lng[tid]     + lnb[tid];
        float y1 = (x1-mean)*rstd*lng[tid+256] + lnb[tid+256];
        gs[tid]     = 0.5f*y0*(1.f+erff(y0*0.70710678118654752f));
        gs[tid+256] = 0.5f*y1*(1.f+erff(y1*0.70710678118654752f));
    }
    __syncthreads();
    for (int m=w; m<MM; m+=8){
        float acc = 0.f;
#pragma unroll
        for (int i=0;i<16;i++){
            int d = lane + 32*i;
            acc += gs[d]*w2[m*512+d];
        }
        acc = warp_sum(acc);
        if (lane==0) qp[r*MM+m] = acc + b2[m];
    }
}

// ---------------- decomposer: abs-topk + normalize + write [B,N,D,M] -------
__global__ void __launch_bounds__(256) decompose_kernel(
    const float* __restrict__ F, const float* __restrict__ tpl,
    const float* __restrict__ qp, const int* __restrict__ kptr,
    float* __restrict__ out)
{
    const int r = blockIdx.x;
    const int tid = threadIdx.x, lane = tid&31, w = tid>>5;
    __shared__ float fs[512];
    __shared__ int hist[8][256];
    __shared__ unsigned int thr_s[MM];
    __shared__ float scale_s[MM];
    __shared__ unsigned int eqmask_s[MM][16];

    fs[tid]     = F[(size_t)r*512 + tid];
    fs[tid+256] = F[(size_t)r*512 + tid + 256];
    __syncthreads();

    const int kval = *kptr;   // 51

    for (int m=w; m<MM; m+=8){
        // cache products + abs bit patterns
        float p[16]; unsigned int u[16];
#pragma unroll
        for (int i=0;i<16;i++){
            int d = lane + 32*i;
            p[i] = fs[d]*tpl[m*512+d];
            u[i] = __float_as_uint(fabsf(p[i]));
        }
        // exact radix select of k-th largest (31 useful bits: 8/8/8/7)
        unsigned int pref=0u, pmask=0u; int kk = kval;
        const int shifts[4]  = {23,15,7,0};
        const unsigned int dmasks[4] = {0xFFu,0xFFu,0xFFu,0x7Fu};
#pragma unroll
        for (int ps=0; ps<4; ps++){
            const int sh = shifts[ps]; const unsigned int dm = dmasks[ps];
            for (int bI=lane; bI<256; bI+=32) hist[w][bI]=0;
            __syncwarp();
#pragma unroll
            for (int i=0;i<16;i++){
                if ((u[i] & pmask) == pref)
                    atomicAdd(&hist[w][(u[i]>>sh)&dm], 1);
            }
            __syncwarp();
            // descending suffix scan: lane l owns digits 255-8l .. 248-8l
            int base = 255 - 8*lane;
            int s8 = 0;
#pragma unroll
            for (int j=0;j<8;j++) s8 += hist[w][base-j];
            int incl = s8;
#pragma unroll
            for (int off=1; off<32; off<<=1){
                int v = __shfl_up_sync(0xffffffffu, incl, off);
                if (lane>=off) incl += v;
            }
            int excl = incl - s8;
            int dig = -1, kk2 = 0;
            if (excl < kk && incl >= kk){
                int run = excl;
#pragma unroll
                for (int j=0;j<8;j++){
                    int hc = hist[w][base-j];
                    if (dig<0 && run+hc >= kk){ dig = base-j; kk2 = kk-run; }
                    run += hc;
                }
            }
            unsigned int bal = __ballot_sync(0xffffffffu, dig>=0);
            int src = __ffs(bal)-1;
            dig = __shfl_sync(0xffffffffu, dig, src);
            kk  = __shfl_sync(0xffffffffu, kk2, src);
            pref  |= ((unsigned int)dig) << sh;
            pmask |= dm << sh;
            __syncwarp();
        }
        const unsigned int thr = pref;
        const int needeq = kk;   // equals to take (smallest index first)

        if (lane<16) eqmask_s[m][lane]=0u;
        __syncwarp();
        float ss = 0.f; int eqbase = 0;
#pragma unroll
        for (int i=0;i<16;i++){
            bool eq = (u[i]==thr);
            unsigned int eb = __ballot_sync(0xffffffffu, eq);
            bool esel = eq && (eqbase + __popc(eb & ((1u<<lane)-1u)) < needeq);
            eqbase += __popc(eb);
            unsigned int sb = __ballot_sync(0xffffffffu, esel);
            if (lane==0) eqmask_s[m][i] = sb;
            if (u[i] > thr || esel) ss += p[i]*p[i];
        }
        ss = warp_sum(ss);
        if (lane==0){
            float q = qp[r*MM+m];
            float nrm = fabsf(q)*sqrtf(ss);
            scale_s[m] = q / fmaxf(nrm, 1e-6f);
            thr_s[m]   = thr;
        }
    }
    __syncthreads();

    // output: 10240 consecutive floats per (b,n) tile, fully coalesced
    const size_t obase = (size_t)r * (512*MM);
    for (int lin=tid; lin<512*MM; lin+=256){
        int d = lin / MM, m = lin - d*MM;
        float pv = fs[d]*tpl[m*512+d];
        unsigned int uu = __float_as_uint(fabsf(pv));
        unsigned int thr = thr_s[m];
        bool sel = (uu > thr) ||
                   (uu == thr && ((eqmask_s[m][d>>5] >> (d&31)) & 1u));
        out[obase + lin] = sel ? pv*scale_s[m] : 0.f;
    }
}

// ---------------- launch ----------------
extern "C" void kernel_launch(void* const* d_in, const int* in_sizes, int n_in,
                              void* d_out, int out_size)
{
    (void)in_sizes; (void)n_in; (void)out_size;
    const float* F     = (const float*)d_in[0];
    const float* in_w  = (const float*)d_in[1];
    const float* in_b  = (const float*)d_in[2];
    const float* out_w = (const float*)d_in[3];
    const float* out_b = (const float*)d_in[4];
    const float* w1    = (const float*)d_in[5];
    const float* b1    = (const float*)d_in[6];
    const float* ln_g  = (const float*)d_in[7];
    const float* ln_b  = (const float*)d_in[8];
    const float* w2    = (const float*)d_in[9];
    const float* b2    = (const float*)d_in[10];
    const float* tpl   = (const float*)d_in[11];
    const int*   kptr  = (const int*)d_in[12];
    float* out = (float*)d_out;

    void *p_qkv, *p_att, *p_enh, *p_h, *p_qp;
    cudaGetSymbolAddress(&p_qkv, g_qkv);
    cudaGetSymbolAddress(&p_att, g_att);
    cudaGetSymbolAddress(&p_enh, g_enh);
    cudaGetSymbolAddress(&p_h,   g_h);
    cudaGetSymbolAddress(&p_qp,  g_qp);
    float* qkv = (float*)p_qkv;
    float* att = (float*)p_att;
    float* enh = (float*)p_enh;
    float* hb  = (float*)p_h;
    float* qp  = (float*)p_qp;

    // 1) qkv = F @ in_proj_w^T + b        [3136,1536]
    gemm_nt<false><<<dim3(1536/128, RTOT/64), 256>>>(F, in_w, in_b, nullptr, qkv, 512, 1536);
    // 2) attention -> g_att
    attn_kernel<<<dim3(7, HH, BB), 256>>>();
    // 3) F_enh = att @ out_w^T + out_b + F
    gemm_nt<true><<<dim3(512/128, RTOT/64), 256>>>(att, out_w, out_b, F, enh, 512, 512);
    // 4) h = F_enh @ w1^T + b1
    gemm_nt<false><<<dim3(512/128, RTOT/64), 256>>>(enh, w1, b1, nullptr, hb, 512, 512);
    // 5) LN + GELU + w2 -> Qp
    ln_gelu_qp<<<RTOT, 256>>>(hb, ln_g, ln_b, w2, b2, qp);
    // 6) decompose: topk + normalize + write [B,N,D,M]
    decompose_kernel<<<RTOT, 256>>>(F, tpl, qp, kptr, out);
}

// round 2
// speedup vs baseline: 1.0376x; 1.0376x over previous
#include <cuda_runtime.h>
#include <math.h>
#include <stdint.h>

#define BB 16
#define NN 196
#define DD 512
#define MM 20
#define HH 8
#define HD 64
#define RTOT (BB*NN)   /* 3136 */

// ---------------- scratch (device globals; no allocation) ----------------
__device__ float g_qkv[RTOT*3*DD];   // [r][1536]
__device__ float g_att[RTOT*DD];     // attention output (pre out-proj)
__device__ float g_enh[RTOT*DD];     // F_enh
__device__ float g_h[RTOT*DD];       // after w1 (pre-LN)
__device__ float g_qp[RTOT*MM];      // Qp

// ---------------- helpers ----------------
__device__ __forceinline__ float warp_sum(float v){
#pragma unroll
    for (int off=16; off; off>>=1) v += __shfl_xor_sync(0xffffffffu, v, off);
    return v;
}
__device__ __forceinline__ float warp_max(float v){
#pragma unroll
    for (int off=16; off; off>>=1) v = fmaxf(v, __shfl_xor_sync(0xffffffffu, v, off));
    return v;
}

// ---------------- GEMM: C[r][o] = sum_k A[r][k]*W[o][k] + bias[o] (+res) ----
// BM=128, BN in {128,64}, BK=16, 256 threads, 8x8 (or 4x8) microtile,
// double-buffered shared with register staging. One sync per K-tile.
template<int BN, bool RES>
__global__ void __launch_bounds__(256) gemm_tile(
    const float* __restrict__ A, const float* __restrict__ W,
    const float* __restrict__ bias, const float* __restrict__ res,
    float* __restrict__ C, int R, int K, int O)
{
    constexpr int BM = 128, BK = 16;
    constexpr int TX = BN/8;       // threads along N (16 or 8)
    constexpr int TY = 256/TX;     // threads along M (16 or 32)
    constexpr int RM = BM/TY;      // rows per thread (8 or 4)
    constexpr int NA = 2;          // A float4 per thread per stage
    constexpr int NB = BN/64;      // B float4 per thread per stage

    __shared__ __align__(16) float As[2][BK][BM+4];
    __shared__ __align__(16) float Bs[2][BK][BN+4];

    const int tid = threadIdx.x;
    const int rb = blockIdx.y*BM, ob = blockIdx.x*BN;
    const int tx = tid % TX, ty = tid / TX;

    float acc[RM][8];
#pragma unroll
    for (int i=0;i<RM;i++)
#pragma unroll
        for (int j=0;j<8;j++) acc[i][j]=0.f;

    float4 ar[NA], br[NB];

    // ---- stage 0 load ----
    {
        const int k0 = 0;
#pragma unroll
        for (int i=0;i<NA;i++){
            int f = tid + i*256; int row = f>>2, kq = f&3;
            int gr = rb+row; if (gr>=R) gr = R-1;
            ar[i] = *(const float4*)&A[(size_t)gr*K + k0 + kq*4];
        }
#pragma unroll
        for (int i=0;i<NB;i++){
            int f = tid + i*256; int row = f>>2, kq = f&3;
            br[i] = *(const float4*)&W[(size_t)(ob+row)*K + k0 + kq*4];
        }
#pragma unroll
        for (int i=0;i<NA;i++){
            int f = tid + i*256; int row = f>>2, kq = f&3;
            As[0][kq*4+0][row]=ar[i].x; As[0][kq*4+1][row]=ar[i].y;
            As[0][kq*4+2][row]=ar[i].z; As[0][kq*4+3][row]=ar[i].w;
        }
#pragma unroll
        for (int i=0;i<NB;i++){
            int f = tid + i*256; int row = f>>2, kq = f&3;
            Bs[0][kq*4+0][row]=br[i].x; Bs[0][kq*4+1][row]=br[i].y;
            Bs[0][kq*4+2][row]=br[i].z; Bs[0][kq*4+3][row]=br[i].w;
        }
    }
    __syncthreads();

    const int NT = K/BK;
    for (int kt=0; kt<NT; kt++){
        if (kt+1 < NT){
            const int k0 = (kt+1)*BK;
#pragma unroll
            for (int i=0;i<NA;i++){
                int f = tid + i*256; int row = f>>2, kq = f&3;
                int gr = rb+row; if (gr>=R) gr = R-1;
                ar[i] = *(const float4*)&A[(size_t)gr*K + k0 + kq*4];
            }
#pragma unroll
            for (int i=0;i<NB;i++){
                int f = tid + i*256; int row = f>>2, kq = f&3;
                br[i] = *(const float4*)&W[(size_t)(ob+row)*K + k0 + kq*4];
            }
        }
        const int s = kt & 1;
#pragma unroll
        for (int kk=0;kk<BK;kk++){
            float a[RM], b[8];
#pragma unroll
            for (int q=0;q<RM/4;q++){
                float4 av = *(const float4*)&As[s][kk][ty*RM+q*4];
                a[q*4+0]=av.x; a[q*4+1]=av.y; a[q*4+2]=av.z; a[q*4+3]=av.w;
            }
            {
                float4 b0 = *(const float4*)&Bs[s][kk][tx*8];
                float4 b1 = *(const float4*)&Bs[s][kk][tx*8+4];
                b[0]=b0.x;b[1]=b0.y;b[2]=b0.z;b[3]=b0.w;
                b[4]=b1.x;b[5]=b1.y;b[6]=b1.z;b[7]=b1.w;
            }
#pragma unroll
            for (int i=0;i<RM;i++)
#pragma unroll
                for (int j=0;j<8;j++) acc[i][j] += a[i]*b[j];
        }
        if (kt+1 < NT){
            const int s2 = (kt+1)&1;
#pragma unroll
            for (int i=0;i<NA;i++){
                int f = tid + i*256; int row = f>>2, kq = f&3;
                As[s2][kq*4+0][row]=ar[i].x; As[s2][kq*4+1][row]=ar[i].y;
                As[s2][kq*4+2][row]=ar[i].z; As[s2][kq*4+3][row]=ar[i].w;
            }
#pragma unroll
            for (int i=0;i<NB;i++){
                int f = tid + i*256; int row = f>>2, kq = f&3;
                Bs[s2][kq*4+0][row]=br[i].x; Bs[s2][kq*4+1][row]=br[i].y;
                Bs[s2][kq*4+2][row]=br[i].z; Bs[s2][kq*4+3][row]=br[i].w;
            }
        }
        __syncthreads();
    }

    // ---- epilogue ----
    float4 bi0 = *(const float4*)&bias[ob + tx*8];
    float4 bi1 = *(const float4*)&bias[ob + tx*8 + 4];
#pragma unroll
    for (int i=0;i<RM;i++){
        int r = rb + ty*RM + i;
        if (r < R){
            size_t base = (size_t)r*O + ob + tx*8;
            float4 v0 = make_float4(acc[i][0]+bi0.x, acc[i][1]+bi0.y,
                                    acc[i][2]+bi0.z, acc[i][3]+bi0.w);
            float4 v1 = make_float4(acc[i][4]+bi1.x, acc[i][5]+bi1.y,
                                    acc[i][6]+bi1.z, acc[i][7]+bi1.w);
            if (RES){
                float4 r0 = *(const float4*)&res[base];
                float4 r1 = *(const float4*)&res[base+4];
                v0.x+=r0.x; v0.y+=r0.y; v0.z+=r0.z; v0.w+=r0.w;
                v1.x+=r1.x; v1.y+=r1.y; v1.z+=r1.z; v1.w+=r1.w;
            }
            *(float4*)&C[base]   = v0;
            *(float4*)&C[base+4] = v1;
        }
    }
}

// ---------------- attention: block per (qchunk, head, batch) ----------------
// 28 query rows per block, streaming softmax over 4 tiles of 49 keys.
__global__ void __launch_bounds__(256) attn_kernel()
{
    const int qc = blockIdx.x, h = blockIdx.y, b = blockIdx.z;
    const int r0 = qc*28;
    __shared__ __align__(16) float Qs[28*68];
    __shared__ __align__(16) float Ks[49*68];
    __shared__ __align__(16) float Vs[49*68];
    __shared__ float S[28*52];
    const int tid = threadIdx.x, lane = tid & 31, w = tid >> 5;

    for (int idx=tid; idx<28*64; idx+=256){
        int row = idx>>6, kx = idx&63;
        Qs[row*68+kx] = g_qkv[(size_t)(b*NN + r0+row)*1536 + h*64 + kx];
    }

    const int nrows = (w<4)?4:3;
    float mrun[4], lrun[4], o0[4], o1[4];
#pragma unroll
    for (int rr=0; rr<4; rr++){ mrun[rr]=-1e30f; lrun[rr]=0.f; o0[rr]=0.f; o1[rr]=0.f; }

    for (int t=0;t<4;t++){
        if (t>0) __syncthreads();            // previous row-phase done before overwrite
        for (int idx=tid; idx<49*64; idx+=256){
            int j = idx>>6, kx = idx&63;
            int nk = t*49 + j;
            size_t base = (size_t)(b*NN + nk)*1536 + h*64 + kx;
            Ks[j*68+kx] = g_qkv[base + 512];
            Vs[j*68+kx] = g_qkv[base + 1024];
        }
        __syncthreads();
        // scores
        for (int i=tid; i<28*49; i+=256){
            int row = i/49, j = i - row*49;
            const float4* q4 = (const float4*)&Qs[row*68];
            const float4* k4 = (const float4*)&Ks[j*68];
            float acc = 0.f;
#pragma unroll
            for (int kx=0; kx<16; kx++){
                float4 qa = q4[kx], ka = k4[kx];
                acc += qa.x*ka.x + qa.y*ka.y + qa.z*ka.z + qa.w*ka.w;
            }
            S[row*52+j] = acc * 0.125f;
        }
        __syncthreads();
        // row phase: warp w owns rows w, w+8, w+16, (w+24)
        for (int rr=0; rr<nrows; rr++){
            int row = w + 8*rr;
            float s0 = (lane<49) ? S[row*52+lane]    : -1e30f;
            float s1 = (lane<17) ? S[row*52+lane+32] : -1e30f;
            float tm = warp_max(fmaxf(s0,s1));
            float mnew = fmaxf(mrun[rr], tm);
            float alpha = __expf(mrun[rr]-mnew);
            float p0 = (lane<49) ? __expf(s0-mnew) : 0.f;
            float p1 = (lane<17) ? __expf(s1-mnew) : 0.f;
            float psum = warp_sum(p0+p1);
            lrun[rr] = lrun[rr]*alpha + psum;
            mrun[rr] = mnew;
            if (lane<49) S[row*52+lane]    = p0;
            if (lane<17) S[row*52+lane+32] = p1;
            __syncwarp();
            float a0 = o0[rr]*alpha, a1 = o1[rr]*alpha;
#pragma unroll 7
            for (int j=0;j<49;j++){
                float pj = S[row*52+j];
                a0 += pj * Vs[j*68+lane];
                a1 += pj * Vs[j*68+lane+32];
            }
            o0[rr]=a0; o1[rr]=a1;
        }
    }
    for (int rr=0; rr<nrows; rr++){
        int row = w + 8*rr;
        float inv = 1.f/lrun[rr];
        size_t base = (size_t)(b*NN + r0+row)*512 + h*64;
        g_att[base+lane]    = o0[rr]*inv;
        g_att[base+lane+32] = o1[rr]*inv;
    }
}

// ---------------- LayerNorm + GELU(exact) + w2 -> Qp ----------------
__global__ void __launch_bounds__(256) ln_gelu_qp(
    const float* __restrict__ hin, const float* __restrict__ lng,
    const float* __restrict__ lnb, const float* __restrict__ w2,
    const float* __restrict__ b2, float* __restrict__ qp)
{
    const int r = blockIdx.x, tid = threadIdx.x, lane = tid&31, w = tid>>5;
    __shared__ float gs[512];
    __shared__ float red[16];
    float x0 = hin[(size_t)r*512 + tid];
    float x1 = hin[(size_t)r*512 + tid + 256];
    float s  = warp_sum(x0 + x1);
    float sq = warp_sum(x0*x0 + x1*x1);
    if (lane==0){ red[w]=s; red[w+8]=sq; }
    __syncthreads();
    if (tid==0){
        float S=0,Q=0;
#pragma unroll
        for (int i=0;i<8;i++){ S+=red[i]; Q+=red[i+8]; }
        red[0]=S; red[1]=Q;
    }
    __syncthreads();
    float mean = red[0]*(1.f/512.f);
    float var  = red[1]*(1.f/512.f) - mean*mean;
    float rstd = rsqrtf(var + 1e-5f);

    {
        float y0 = (x0-mean)*rstd*lng[tid]     + lnb[tid];
        float y1 = (x1-mean)*rstd*lng[tid+256] + lnb[tid+256];
        gs[tid]     = 0.5f*y0*(1.f+erff(y0*0.70710678118654752f));
        gs[tid+256] = 0.5f*y1*(1.f+erff(y1*0.70710678118654752f));
    }
    __syncthreads();
    for (int m=w; m<MM; m+=8){
        float acc = 0.f;
#pragma unroll
        for (int i=0;i<16;i++){
            int d = lane + 32*i;
            acc += gs[d]*w2[m*512+d];
        }
        acc = warp_sum(acc);
        if (lane==0) qp[r*MM+m] = acc + b2[m];
    }
}

// ---------------- decomposer: abs-topk + normalize + write [B,N,D,M] -------
__global__ void __launch_bounds__(256) decompose_kernel(
    const float* __restrict__ F, const float* __restrict__ tpl,
    const float* __restrict__ qp, const int* __restrict__ kptr,
    float* __restrict__ out)
{
    const int r = blockIdx.x;
    const int tid = threadIdx.x, lane = tid&31, w = tid>>5;
    __shared__ float fs[512];
    __shared__ int hist[8][256];
    __shared__ unsigned int thr_s[MM];
    __shared__ float scale_s[MM];
    __shared__ unsigned int eqmask_s[MM][16];

    fs[tid]     = F[(size_t)r*512 + tid];
    fs[tid+256] = F[(size_t)r*512 + tid + 256];
    __syncthreads();

    const int kval = *kptr;   // 51

    for (int m=w; m<MM; m+=8){
        // cache products + abs bit patterns
        float p[16]; unsigned int u[16];
#pragma unroll
        for (int i=0;i<16;i++){
            int d = lane + 32*i;
            p[i] = fs[d]*tpl[m*512+d];
            u[i] = __float_as_uint(fabsf(p[i]));
        }
        // exact radix select of k-th largest (31 useful bits: 8/8/8/7)
        unsigned int pref=0u, pmask=0u; int kk = kval;
        const int shifts[4]  = {23,15,7,0};
        const unsigned int dmasks[4] = {0xFFu,0xFFu,0xFFu,0x7Fu};
#pragma unroll
        for (int ps=0; ps<4; ps++){
            const int sh = shifts[ps]; const unsigned int dm = dmasks[ps];
            for (int bI=lane; bI<256; bI+=32) hist[w][bI]=0;
            __syncwarp();
#pragma unroll
            for (int i=0;i<16;i++){
                if ((u[i] & pmask) == pref)
                    atomicAdd(&hist[w][(u[i]>>sh)&dm], 1);
            }
            __syncwarp();
            // descending suffix scan: lane l owns digits 255-8l .. 248-8l
            int base = 255 - 8*lane;
            int s8 = 0;
#pragma unroll
            for (int j=0;j<8;j++) s8 += hist[w][base-j];
            int incl = s8;
#pragma unroll
            for (int off=1; off<32; off<<=1){
                int v = __shfl_up_sync(0xffffffffu, incl, off);
                if (lane>=off) incl += v;
            }
            int excl = incl - s8;
            int dig = -1, kk2 = 0;
            if (excl < kk && incl >= kk){
                int run = excl;
#pragma unroll
                for (int j=0;j<8;j++){
                    int hc = hist[w][base-j];
                    if (dig<0 && run+hc >= kk){ dig = base-j; kk2 = kk-run; }
                    run += hc;
                }
            }
            unsigned int bal = __ballot_sync(0xffffffffu, dig>=0);
            int src = __ffs(bal)-1;
            dig = __shfl_sync(0xffffffffu, dig, src);
            kk  = __shfl_sync(0xffffffffu, kk2, src);
            pref  |= ((unsigned int)dig) << sh;
            pmask |= dm << sh;
            __syncwarp();
        }
        const unsigned int thr = pref;
        const int needeq = kk;   // equals to take (smallest index first)

        if (lane<16) eqmask_s[m][lane]=0u;
        __syncwarp();
        float ss = 0.f; int eqbase = 0;
#pragma unroll
        for (int i=0;i<16;i++){
            bool eq = (u[i]==thr);
            unsigned int eb = __ballot_sync(0xffffffffu, eq);
            bool esel = eq && (eqbase + __popc(eb & ((1u<<lane)-1u)) < needeq);
            eqbase += __popc(eb);
            unsigned int sb = __ballot_sync(0xffffffffu, esel);
            if (lane==0) eqmask_s[m][i] = sb;
            if (u[i] > thr || esel) ss += p[i]*p[i];
        }
        ss = warp_sum(ss);
        if (lane==0){
            float q = qp[r*MM+m];
            float nrm = fabsf(q)*sqrtf(ss);
            scale_s[m] = q / fmaxf(nrm, 1e-6f);
            thr_s[m]   = thr;
        }
    }
    __syncthreads();

    // output: 10240 consecutive floats per (b,n) tile, fully coalesced
    const size_t obase = (size_t)r * (512*MM);
    for (int lin=tid; lin<512*MM; lin+=256){
        int d = lin / MM, m = lin - d*MM;
        float pv = fs[d]*tpl[m*512+d];
        unsigned int uu = __float_as_uint(fabsf(pv));
        unsigned int thr = thr_s[m];
        bool sel = (uu > thr) ||
                   (uu == thr && ((eqmask_s[m][d>>5] >> (d&31)) & 1u));
        out[obase + lin] = sel ? pv*scale_s[m] : 0.f;
    }
}

// ---------------- launch ----------------
extern "C" void kernel_launch(void* const* d_in, const int* in_sizes, int n_in,
                              void* d_out, int out_size)
{
    (void)in_sizes; (void)n_in; (void)out_size;
    const float* F     = (const float*)d_in[0];
    const float* in_w  = (const float*)d_in[1];
    const float* in_b  = (const float*)d_in[2];
    const float* out_w = (const float*)d_in[3];
    const float* out_b = (const float*)d_in[4];
    const float* w1    = (const float*)d_in[5];
    const float* b1    = (const float*)d_in[6];
    const float* ln_g  = (const float*)d_in[7];
    const float* ln_b  = (const float*)d_in[8];
    const float* w2    = (const float*)d_in[9];
    const float* b2    = (const float*)d_in[10];
    const float* tpl   = (const float*)d_in[11];
    const int*   kptr  = (const int*)d_in[12];
    float* out = (float*)d_out;

    void *p_qkv, *p_att, *p_enh, *p_h, *p_qp;
    cudaGetSymbolAddress(&p_qkv, g_qkv);
    cudaGetSymbolAddress(&p_att, g_att);
    cudaGetSymbolAddress(&p_enh, g_enh);
    cudaGetSymbolAddress(&p_h,   g_h);
    cudaGetSymbolAddress(&p_qp,  g_qp);
    float* qkv = (float*)p_qkv;
    float* att = (float*)p_att;
    float* enh = (float*)p_enh;
    float* hb  = (float*)p_h;
    float* qp  = (float*)p_qp;

    const int gy = (RTOT + 127) / 128;   // 25

    // 1) qkv = F @ in_proj_w^T + b        [3136,1536]
    gemm_tile<128,false><<<dim3(1536/128, gy), 256>>>(F, in_w, in_b, nullptr, qkv, RTOT, 512, 1536);
    // 2) attention -> g_att
    attn_kernel<<<dim3(7, HH, BB), 256>>>();
    // 3) F_enh = att @ out_w^T + out_b + F
    gemm_tile<64,true><<<dim3(512/64, gy), 256>>>(att, out_w, out_b, F, enh, RTOT, 512, 512);
    // 4) h = F_enh @ w1^T + b1
    gemm_tile<64,false><<<dim3(512/64, gy), 256>>>(enh, w1, b1, nullptr, hb, RTOT, 512, 512);
    // 5) LN + GELU + w2 -> Qp
    ln_gelu_qp<<<RTOT, 256>>>(hb, ln_g, ln_b, w2, b2, qp);
    // 6) decompose: topk + normalize + write [B,N,D,M]
    decompose_kernel<<<RTOT, 256>>>(F, tpl, qp, kptr, out);
}

// round 5
// speedup vs baseline: 1.2472x; 1.2020x over previous
#include <cuda_runtime.h>
#include <cuda_bf16.h>
#include <math.h>
#include <stdint.h>

#define BB 16
#define NN 196
#define DD 512
#define MM 20
#define HH 8
#define HD 64
#define RTOT (BB*NN)   /* 3136 */

// ---------------- scratch (device globals; no allocation) ----------------
__device__ float g_qkv[RTOT*3*DD];   // [r][1536]
__device__ float g_att[RTOT*DD];     // attention output (pre out-proj)
__device__ float g_enh[RTOT*DD];     // F_enh
__device__ float g_h[RTOT*DD];       // after w1 (pre-LN)
__device__ float g_qp[RTOT*MM];      // Qp

// ---------------- warp helpers ----------------
__device__ __forceinline__ float warp_sum(float v){
#pragma unroll
    for (int off=16; off; off>>=1) v += __shfl_xor_sync(0xffffffffu, v, off);
    return v;
}
__device__ __forceinline__ float warp_max(float v){
#pragma unroll
    for (int off=16; off; off>>=1) v = fmaxf(v, __shfl_xor_sync(0xffffffffu, v, off));
    return v;
}

// ---------------- mma.sync helpers (standard PTX, works on sm_100) --------
__device__ __forceinline__ uint32_t smem_u32(const void* p){
    uint32_t a;
    asm("{ .reg .u64 t; cvta.to.shared.u64 t, %1; cvt.u32.u64 %0, t; }" : "=r"(a) : "l"(p));
    return a;
}
__device__ __forceinline__ void ldm4(uint32_t* r, uint32_t addr){
    asm volatile("ldmatrix.sync.aligned.m8n8.x4.shared.b16 {%0,%1,%2,%3}, [%4];"
        : "=r"(r[0]),"=r"(r[1]),"=r"(r[2]),"=r"(r[3]) : "r"(addr));
}
__device__ __forceinline__ void mma16816(float* c, const uint32_t* a, const uint32_t* b){
    asm volatile("mma.sync.aligned.m16n8k16.row.col.f32.bf16.bf16.f32 "
        "{%0,%1,%2,%3}, {%4,%5,%6,%7}, {%8,%9}, {%0,%1,%2,%3};"
        : "+f"(c[0]),"+f"(c[1]),"+f"(c[2]),"+f"(c[3])
        : "r"(a[0]),"r"(a[1]),"r"(a[2]),"r"(a[3]), "r"(b[0]),"r"(b[1]));
}

// 3-way bf16 cascade split: v = h1 + h2 + h3 + O(2^-27 |v|)
__device__ __forceinline__ void split3(float v, uint32_t& t1, uint32_t& t2, uint32_t& t3){
    __nv_bfloat16 h1 = __float2bfloat16_rn(v);
    float r1 = v - __bfloat162float(h1);
    __nv_bfloat16 h2 = __float2bfloat16_rn(r1);
    float r2 = r1 - __bfloat162float(h2);
    __nv_bfloat16 h3 = __float2bfloat16_rn(r2);
    t1 = (uint32_t)__bfloat16_as_ushort(h1);
    t2 = (uint32_t)__bfloat16_as_ushort(h2);
    t3 = (uint32_t)__bfloat16_as_ushort(h3);
}

// ---------------- tensor-core GEMM (accurate 3-term split) ------------------
// C[r][o] = sum_k A[r][k]*W[o][k] + bias[o] (+res)
// 128x128 tile/CTA, 8 warps (4m x 2n), warp tile 32x64, m16n8k16 bf16.
// Per 32-fp32 k-chunk: six 128x32 bf16 tiles (a1,a2,a3,w1,w2,w3), SW64 rows,
// double buffered. Six accumulated products: a1(w1+w2+w3)+a2(w1+w2)+a3*w1.
// ----------------------------------------------------------------------------
#define TILE_B   8192                 /* 128 rows x 32 bf16 x 2B */
#define STAGE_B  (6*TILE_B)           /* 49152 */
#define GSM_SIZE (2*STAGE_B)          /* 98304 (>= 66048 epilogue staging) */

template<bool RES>
__global__ void __launch_bounds__(256) gemm_mma(
    const float* __restrict__ A, const float* __restrict__ W,
    const float* __restrict__ bias, const float* __restrict__ res,
    float* __restrict__ C, int R, int K, int O)
{
    extern __shared__ __align__(128) char smem[];
    const uint32_t sb = smem_u32(smem);
    const int tid = threadIdx.x, lane = tid & 31, wid = tid >> 5;
    const int rb = blockIdx.y * 128, ob = blockIdx.x * 128;
    const int wm = wid & 3, wn = wid >> 2;

    float acc[2][8][4];
#pragma unroll
    for (int i=0;i<2;i++)
#pragma unroll
        for (int j=0;j<8;j++)
#pragma unroll
            for (int q=0;q<4;q++) acc[i][j][q]=0.f;

    // per-thread chunk slice: float4 index f = tid + j*256, row=f>>3, kq=f&7
    float4 va[4], vw[4];

    // ---- helper: load chunk k0 into regs ----
    auto load_chunk = [&](int k0){
#pragma unroll
        for (int j = 0; j < 4; j++){
            int f = tid + j*256, row = f >> 3, q = f & 7;
            int gr = rb + row; if (gr >= R) gr = R - 1;
            va[j] = *(const float4*)&A[(size_t)gr*K + k0 + q*4];
            vw[j] = *(const float4*)&W[(size_t)(ob + row)*K + k0 + q*4];
        }
    };
    // ---- helper: split + store regs into stage st ----
    auto store_chunk = [&](int st){
        char* base = smem + st*STAGE_B;
#pragma unroll
        for (int j = 0; j < 4; j++){
            int f = tid + j*256;
            uint32_t off = (uint32_t)((f>>3)*64 + (f&7)*8);
            off ^= (off >> 3) & 0x30u;
            uint32_t x1,x2,x3, y1,y2,y3, z1,z2,z3, u1,u2,u3;
            split3(va[j].x, x1,x2,x3); split3(va[j].y, y1,y2,y3);
            split3(va[j].z, z1,z2,z3); split3(va[j].w, u1,u2,u3);
            *(uint2*)(base + 0*TILE_B + off) = make_uint2(x1|(y1<<16), z1|(u1<<16));
            *(uint2*)(base + 1*TILE_B + off) = make_uint2(x2|(y2<<16), z2|(u2<<16));
            *(uint2*)(base + 2*TILE_B + off) = make_uint2(x3|(y3<<16), z3|(u3<<16));
            split3(vw[j].x, x1,x2,x3); split3(vw[j].y, y1,y2,y3);
            split3(vw[j].z, z1,z2,z3); split3(vw[j].w, u1,u2,u3);
            *(uint2*)(base + 3*TILE_B + off) = make_uint2(x1|(y1<<16), z1|(u1<<16));
            *(uint2*)(base + 4*TILE_B + off) = make_uint2(x2|(y2<<16), z2|(u2<<16));
            *(uint2*)(base + 5*TILE_B + off) = make_uint2(x3|(y3<<16), z3|(u3<<16));
        }
    };

    // ---- prologue ----
    load_chunk(0);
    store_chunk(0);
    __syncthreads();

    const int NTc = K / 32;
    const int npair[3] = {3, 2, 1};   // a1*{w1,w2,w3}, a2*{w1,w2}, a3*{w1}

    for (int c = 0; c < NTc; c++){
        if (c+1 < NTc) load_chunk((c+1)*32);

        const uint32_t stg = sb + (uint32_t)(c & 1)*STAGE_B;
#pragma unroll
        for (int ks = 0; ks < 2; ks++){
#pragma unroll
            for (int ai = 0; ai < 3; ai++){
                uint32_t afr[2][4];
#pragma unroll
                for (int mt = 0; mt < 2; mt++){
                    uint32_t row = (uint32_t)(wm*32 + mt*16 + (lane & 15));
                    uint32_t off = row*64 + (uint32_t)(ks*32) + (uint32_t)((lane >> 4) << 4);
                    off ^= (off >> 3) & 0x30u;
                    ldm4(afr[mt], stg + ai*TILE_B + off);
                }
#pragma unroll
                for (int wj = 0; wj < 3; wj++){
                    if (wj >= npair[ai]) break;
                    uint32_t bfr[8][2];
#pragma unroll
                    for (int nt2 = 0; nt2 < 4; nt2++){
                        uint32_t row = (uint32_t)(wn*64 + nt2*16 + ((lane >> 4) << 3) + (lane & 7));
                        uint32_t off = row*64 + (uint32_t)(ks*32) + (uint32_t)(((lane >> 3) & 1) << 4);
                        off ^= (off >> 3) & 0x30u;
                        uint32_t r4[4];
                        ldm4(r4, stg + (3+wj)*TILE_B + off);
                        bfr[nt2*2][0]=r4[0];   bfr[nt2*2][1]=r4[1];
                        bfr[nt2*2+1][0]=r4[2]; bfr[nt2*2+1][1]=r4[3];
                    }
#pragma unroll
                    for (int mt = 0; mt < 2; mt++)
#pragma unroll
                        for (int nt = 0; nt < 8; nt++)
                            mma16816(acc[mt][nt], afr[mt], bfr[nt]);
                }
            }
        }

        if (c+1 < NTc) store_chunk((c+1) & 1);
        __syncthreads();
    }

    // ---- epilogue: stage via SMEM (stride 129) then coalesced global write --
    float* Cs = (float*)smem;
    {
        const int r0 = wm*32 + (lane >> 2);
        const int c0 = wn*64 + 2*(lane & 3);
#pragma unroll
        for (int mt = 0; mt < 2; mt++)
#pragma unroll
            for (int nt = 0; nt < 8; nt++){
                int row = r0 + mt*16, col = c0 + nt*8;
                Cs[row*129 + col]       = acc[mt][nt][0];
                Cs[row*129 + col + 1]   = acc[mt][nt][1];
                Cs[(row+8)*129 + col]   = acc[mt][nt][2];
                Cs[(row+8)*129 + col+1] = acc[mt][nt][3];
            }
    }
    __syncthreads();

    for (int idx = tid; idx < 128*128; idx += 256){
        int row = idx >> 7, c = idx & 127;
        int r = rb + row;
        if (r < R){
            float v = Cs[row*129 + c] + bias[ob + c];
            size_t g = (size_t)r*O + ob + c;
            if (RES) v += res[g];
            C[g] = v;
        }
    }
}

// ---------------- attention: block per (qchunk, head, batch) ----------------
__global__ void __launch_bounds__(256) attn_kernel()
{
    const int qc = blockIdx.x, h = blockIdx.y, b = blockIdx.z;
    const int r0 = qc*28;
    __shared__ __align__(16) float Qs[28*68];
    __shared__ __align__(16) float Ks[49*68];
    __shared__ __align__(16) float Vs[49*68];
    __shared__ float S[28*52];
    const int tid = threadIdx.x, lane = tid & 31, w = tid >> 5;

    for (int idx=tid; idx<28*64; idx+=256){
        int row = idx>>6, kx = idx&63;
        Qs[row*68+kx] = g_qkv[(size_t)(b*NN + r0+row)*1536 + h*64 + kx];
    }

    const int nrows = (w<4)?4:3;
    float mrun[4], lrun[4], o0[4], o1[4];
#pragma unroll
    for (int rr=0; rr<4; rr++){ mrun[rr]=-1e30f; lrun[rr]=0.f; o0[rr]=0.f; o1[rr]=0.f; }

    for (int t=0;t<4;t++){
        if (t>0) __syncthreads();
        for (int idx=tid; idx<49*64; idx+=256){
            int j = idx>>6, kx = idx&63;
            int nk = t*49 + j;
            size_t base = (size_t)(b*NN + nk)*1536 + h*64 + kx;
            Ks[j*68+kx] = g_qkv[base + 512];
            Vs[j*68+kx] = g_qkv[base + 1024];
        }
        __syncthreads();
        for (int i=tid; i<28*49; i+=256){
            int row = i/49, j = i - row*49;
            const float4* q4 = (const float4*)&Qs[row*68];
            const float4* k4 = (const float4*)&Ks[j*68];
            float acc = 0.f;
#pragma unroll
            for (int kx=0; kx<16; kx++){
                float4 qa = q4[kx], ka = k4[kx];
                acc += qa.x*ka.x + qa.y*ka.y + qa.z*ka.z + qa.w*ka.w;
            }
            S[row*52+j] = acc * 0.125f;
        }
        __syncthreads();
        for (int rr=0; rr<nrows; rr++){
            int row = w + 8*rr;
            float s0 = (lane<49) ? S[row*52+lane]    : -1e30f;
            float s1 = (lane<17) ? S[row*52+lane+32] : -1e30f;
            float tm = warp_max(fmaxf(s0,s1));
            float mnew = fmaxf(mrun[rr], tm);
            float alpha = __expf(mrun[rr]-mnew);
            float p0 = (lane<49) ? __expf(s0-mnew) : 0.f;
            float p1 = (lane<17) ? __expf(s1-mnew) : 0.f;
            float psum = warp_sum(p0+p1);
            lrun[rr] = lrun[rr]*alpha + psum;
            mrun[rr] = mnew;
            if (lane<49) S[row*52+lane]    = p0;
            if (lane<17) S[row*52+lane+32] = p1;
            __syncwarp();
            float a0 = o0[rr]*alpha, a1 = o1[rr]*alpha;
#pragma unroll 7
            for (int j=0;j<49;j++){
                float pj = S[row*52+j];
                a0 += pj * Vs[j*68+lane];
                a1 += pj * Vs[j*68+lane+32];
            }
            o0[rr]=a0; o1[rr]=a1;
        }
    }
    for (int rr=0; rr<nrows; rr++){
        int row = w + 8*rr;
        float inv = 1.f/lrun[rr];
        size_t base = (size_t)(b*NN + r0+row)*512 + h*64;
        g_att[base+lane]    = o0[rr]*inv;
        g_att[base+lane+32] = o1[rr]*inv;
    }
}

// ---------------- LayerNorm + GELU(exact) + w2 -> Qp ----------------
__global__ void __launch_bounds__(256) ln_gelu_qp(
    const float* __restrict__ hin, const float* __restrict__ lng,
    const float* __restrict__ lnb, const float* __restrict__ w2,
    const float* __restrict__ b2, float* __restrict__ qp)
{
    const int r = blockIdx.x, tid = threadIdx.x, lane = tid&31, w = tid>>5;
    __shared__ float gs[512];
    __shared__ float red[16];
    float x0 = hin[(size_t)r*512 + tid];
    float x1 = hin[(size_t)r*512 + tid + 256];
    float s  = warp_sum(x0 + x1);
    float sq = warp_sum(x0*x0 + x1*x1);
    if (lane==0){ red[w]=s; red[w+8]=sq; }
    __syncthreads();
    if (tid==0){
        float S=0,Q=0;
#pragma unroll
        for (int i=0;i<8;i++){ S+=red[i]; Q+=red[i+8]; }
        red[0]=S; red[1]=Q;
    }
    __syncthreads();
    float mean = red[0]*(1.f/512.f);
    float var  = red[1]*(1.f/512.f) - mean*mean;
    float rstd = rsqrtf(var + 1e-5f);

    {
        float y0 = (x0-mean)*rstd*lng[tid]     + lnb[tid];
        float y1 = (x1-mean)*rstd*lng[tid+256] + lnb[tid+256];
        gs[tid]     = 0.5f*y0*(1.f+erff(y0*0.70710678118654752f));
        gs[tid+256] = 0.5f*y1*(1.f+erff(y1*0.70710678118654752f));
    }
    __syncthreads();
    for (int m=w; m<MM; m+=8){
        float acc = 0.f;
#pragma unroll
        for (int i=0;i<16;i++){
            int d = lane + 32*i;
            acc += gs[d]*w2[m*512+d];
        }
        acc = warp_sum(acc);
        if (lane==0) qp[r*MM+m] = acc + b2[m];
    }
}

// ---------------- decomposer: abs-topk + normalize + write [B,N,D,M] -------
__global__ void __launch_bounds__(256) decompose_kernel(
    const float* __restrict__ F, const float* __restrict__ tpl,
    const float* __restrict__ qp, const int* __restrict__ kptr,
    float* __restrict__ out)
{
    const int r = blockIdx.x;
    const int tid = threadIdx.x, lane = tid&31, w = tid>>5;
    __shared__ float fs[512];
    __shared__ int hist[8][256];
    __shared__ unsigned int thr_s[MM];
    __shared__ float scale_s[MM];
    __shared__ unsigned int eqmask_s[MM][16];

    fs[tid]     = F[(size_t)r*512 + tid];
    fs[tid+256] = F[(size_t)r*512 + tid + 256];
    __syncthreads();

    const int kval = *kptr;   // 51

    for (int m=w; m<MM; m+=8){
        float p[16]; unsigned int u[16];
#pragma unroll
        for (int i=0;i<16;i++){
            int d = lane + 32*i;
            p[i] = fs[d]*tpl[m*512+d];
            u[i] = __float_as_uint(fabsf(p[i]));
        }
        unsigned int pref=0u, pmask=0u; int kk = kval;
        const int shifts[4]  = {23,15,7,0};
        const unsigned int dmasks[4] = {0xFFu,0xFFu,0xFFu,0x7Fu};
#pragma unroll
        for (int ps=0; ps<4; ps++){
            const int sh = shifts[ps]; const unsigned int dm = dmasks[ps];
            for (int bI=lane; bI<256; bI+=32) hist[w][bI]=0;
            __syncwarp();
#pragma unroll
            for (int i=0;i<16;i++){
                if ((u[i] & pmask) == pref)
                    atomicAdd(&hist[w][(u[i]>>sh)&dm], 1);
            }
            __syncwarp();
            int base = 255 - 8*lane;
            int s8 = 0;
#pragma unroll
            for (int j=0;j<8;j++) s8 += hist[w][base-j];
            int incl = s8;
#pragma unroll
            for (int off=1; off<32; off<<=1){
                int v = __shfl_up_sync(0xffffffffu, incl, off);
                if (lane>=off) incl += v;
            }
            int excl = incl - s8;
            int dig = -1, kk2 = 0;
            if (excl < kk && incl >= kk){
                int run = excl;
#pragma unroll
                for (int j=0;j<8;j++){
                    int hc = hist[w][base-j];
                    if (dig<0 && run+hc >= kk){ dig = base-j; kk2 = kk-run; }
                    run += hc;
                }
            }
            unsigned int bal = __ballot_sync(0xffffffffu, dig>=0);
            int src = __ffs(bal)-1;
            dig = __shfl_sync(0xffffffffu, dig, src);
            kk  = __shfl_sync(0xffffffffu, kk2, src);
            pref  |= ((unsigned int)dig) << sh;
            pmask |= dm << sh;
            __syncwarp();
        }
        const unsigned int thr = pref;
        const int needeq = kk;

        if (lane<16) eqmask_s[m][lane]=0u;
        __syncwarp();
        float ss = 0.f; int eqbase = 0;
#pragma unroll
        for (int i=0;i<16;i++){
            bool eq = (u[i]==thr);
            unsigned int eb = __ballot_sync(0xffffffffu, eq);
            bool esel = eq && (eqbase + __popc(eb & ((1u<<lane)-1u)) < needeq);
            eqbase += __popc(eb);
            unsigned int sb2 = __ballot_sync(0xffffffffu, esel);
            if (lane==0) eqmask_s[m][i] = sb2;
            if (u[i] > thr || esel) ss += p[i]*p[i];
        }
        ss = warp_sum(ss);
        if (lane==0){
            float q = qp[r*MM+m];
            float nrm = fabsf(q)*sqrtf(ss);
            scale_s[m] = q / fmaxf(nrm, 1e-6f);
            thr_s[m]   = thr;
        }
    }
    __syncthreads();

    const size_t obase = (size_t)r * (512*MM);
    for (int lin=tid; lin<512*MM; lin+=256){
        int d = lin / MM, m = lin - d*MM;
        float pv = fs[d]*tpl[m*512+d];
        unsigned int uu = __float_as_uint(fabsf(pv));
        unsigned int thr = thr_s[m];
        bool sel = (uu > thr) ||
                   (uu == thr && ((eqmask_s[m][d>>5] >> (d&31)) & 1u));
        out[obase + lin] = sel ? pv*scale_s[m] : 0.f;
    }
}

// ---------------- launch ----------------
extern "C" void kernel_launch(void* const* d_in, const int* in_sizes, int n_in,
                              void* d_out, int out_size)
{
    (void)in_sizes; (void)n_in; (void)out_size;
    const float* F     = (const float*)d_in[0];
    const float* in_w  = (const float*)d_in[1];
    const float* in_b  = (const float*)d_in[2];
    const float* out_w = (const float*)d_in[3];
    const float* out_b = (const float*)d_in[4];
    const float* w1    = (const float*)d_in[5];
    const float* b1    = (const float*)d_in[6];
    const float* ln_g  = (const float*)d_in[7];
    const float* ln_b  = (const float*)d_in[8];
    const float* w2    = (const float*)d_in[9];
    const float* b2    = (const float*)d_in[10];
    const float* tpl   = (const float*)d_in[11];
    const int*   kptr  = (const int*)d_in[12];
    float* out = (float*)d_out;

    void *p_qkv, *p_att, *p_enh, *p_h, *p_qp;
    cudaGetSymbolAddress(&p_qkv, g_qkv);
    cudaGetSymbolAddress(&p_att, g_att);
    cudaGetSymbolAddress(&p_enh, g_enh);
    cudaGetSymbolAddress(&p_h,   g_h);
    cudaGetSymbolAddress(&p_qp,  g_qp);
    float* qkv = (float*)p_qkv;
    float* att = (float*)p_att;
    float* enh = (float*)p_enh;
    float* hb  = (float*)p_h;
    float* qp  = (float*)p_qp;

    cudaFuncSetAttribute((const void*)gemm_mma<false>,
                         cudaFuncAttributeMaxDynamicSharedMemorySize, GSM_SIZE);
    cudaFuncSetAttribute((const void*)gemm_mma<true>,
                         cudaFuncAttributeMaxDynamicSharedMemorySize, GSM_SIZE);

    const int gy = (RTOT + 127) / 128;   // 25

    // 1) qkv = F @ in_proj_w^T + b        [3136,1536]
    gemm_mma<false><<<dim3(1536/128, gy), 256, GSM_SIZE>>>(F, in_w, in_b, nullptr, qkv, RTOT, 512, 1536);
    // 2) attention -> g_att
    attn_kernel<<<dim3(7, HH, BB), 256>>>();
    // 3) F_enh = att @ out_w^T + out_b + F
    gemm_mma<true><<<dim3(512/128, gy), 256, GSM_SIZE>>>(att, out_w, out_b, F, enh, RTOT, 512, 512);
    // 4) h = F_enh @ w1^T + b1
    gemm_mma<false><<<dim3(512/128, gy), 256, GSM_SIZE>>>(enh, w1, b1, nullptr, hb, RTOT, 512, 512);
    // 5) LN + GELU + w2 -> Qp
    ln_gelu_qp<<<RTOT, 256>>>(hb, ln_g, ln_b, w2, b2, qp);
    // 6) decompose: topk + normalize + write [B,N,D,M]
    decompose_kernel<<<RTOT, 256>>>(F, tpl, qp, kptr, out);
}

// round 6
// speedup vs baseline: 1.4857x; 1.1912x over previous
#include <cuda_runtime.h>
#include <cuda_bf16.h>
#include <math.h>
#include <stdint.h>

#define BB 16
#define NN 196
#define DD 512
#define MM 20
#define HH 8
#define HD 64
#define RTOT (BB*NN)   /* 3136 */

// ---------------- scratch (device globals; no allocation) ----------------
__device__ float g_qkv[RTOT*3*DD];   // [r][1536]
__device__ float g_att[RTOT*DD];     // attention output (pre out-proj)
__device__ float g_enh[RTOT*DD];     // F_enh
__device__ float g_h[RTOT*DD];       // after w1 (pre-LN)
__device__ float g_qp[RTOT*MM];      // Qp

// ---------------- warp helpers ----------------
__device__ __forceinline__ float warp_sum(float v){
#pragma unroll
    for (int off=16; off; off>>=1) v += __shfl_xor_sync(0xffffffffu, v, off);
    return v;
}
__device__ __forceinline__ float warp_max(float v){
#pragma unroll
    for (int off=16; off; off>>=1) v = fmaxf(v, __shfl_xor_sync(0xffffffffu, v, off));
    return v;
}

// ---------------- mma.sync helpers (standard PTX, works on sm_100) --------
__device__ __forceinline__ uint32_t smem_u32(const void* p){
    uint32_t a;
    asm("{ .reg .u64 t; cvta.to.shared.u64 t, %1; cvt.u32.u64 %0, t; }" : "=r"(a) : "l"(p));
    return a;
}
__device__ __forceinline__ void ldm4(uint32_t* r, uint32_t addr){
    asm volatile("ldmatrix.sync.aligned.m8n8.x4.shared.b16 {%0,%1,%2,%3}, [%4];"
        : "=r"(r[0]),"=r"(r[1]),"=r"(r[2]),"=r"(r[3]) : "r"(addr));
}
__device__ __forceinline__ void mma16816(float* c, const uint32_t* a, const uint32_t* b){
    asm volatile("mma.sync.aligned.m16n8k16.row.col.f32.bf16.bf16.f32 "
        "{%0,%1,%2,%3}, {%4,%5,%6,%7}, {%8,%9}, {%0,%1,%2,%3};"
        : "+f"(c[0]),"+f"(c[1]),"+f"(c[2]),"+f"(c[3])
        : "r"(a[0]),"r"(a[1]),"r"(a[2]),"r"(a[3]), "r"(b[0]),"r"(b[1]));
}

// 3-way bf16 cascade split: v = h1 + h2 + h3 + O(2^-27 |v|)
__device__ __forceinline__ void split3(float v, uint32_t& t1, uint32_t& t2, uint32_t& t3){
    __nv_bfloat16 h1 = __float2bfloat16_rn(v);
    float r1 = v - __bfloat162float(h1);
    __nv_bfloat16 h2 = __float2bfloat16_rn(r1);
    float r2 = r1 - __bfloat162float(h2);
    __nv_bfloat16 h3 = __float2bfloat16_rn(r2);
    t1 = (uint32_t)__bfloat16_as_ushort(h1);
    t2 = (uint32_t)__bfloat16_as_ushort(h2);
    t3 = (uint32_t)__bfloat16_as_ushort(h3);
}

// ---------------- tensor-core GEMM (accurate 3-term split) ------------------
// C[r][o] = sum_k A[r][k]*W[o][k] + bias[o] (+res)
// 64x128 tile/CTA, 8 warps (2m x 4n), warp tile 32x32, m16n8k16 bf16.
// Per 32-fp32 k-chunk: a1,a2,a3 (64x32 bf16) + w1,w2,w3 (128x32 bf16), SW64
// rows, double buffered. Products: a1(w1+w2+w3)+a2(w1+w2)+a3*w1.
// ----------------------------------------------------------------------------
#define TILE_A   4096                 /* 64 rows x 32 bf16 x 2B */
#define TILE_W   8192                 /* 128 rows x 32 bf16 x 2B */
#define STAGE_B  (3*TILE_A + 3*TILE_W)   /* 36864 */
#define GSM_SIZE (2*STAGE_B)             /* 73728 (>= 64*129*4 epilogue) */

template<bool RES>
__global__ void __launch_bounds__(256) gemm_mma(
    const float* __restrict__ A, const float* __restrict__ W,
    const float* __restrict__ bias, const float* __restrict__ res,
    float* __restrict__ C, int R, int K, int O)
{
    extern __shared__ __align__(128) char smem[];
    const uint32_t sb = smem_u32(smem);
    const int tid = threadIdx.x, lane = tid & 31, wid = tid >> 5;
    const int rb = blockIdx.y * 64, ob = blockIdx.x * 128;
    const int wm = wid & 1, wn = wid >> 1;   // warp tile: rows wm*32, cols wn*32

    float acc[2][4][4];
#pragma unroll
    for (int i=0;i<2;i++)
#pragma unroll
        for (int j=0;j<4;j++)
#pragma unroll
            for (int q=0;q<4;q++) acc[i][j][q]=0.f;

    float4 va[2], vw[4];

    auto load_chunk = [&](int k0){
#pragma unroll
        for (int j = 0; j < 2; j++){
            int f = tid + j*256, row = f >> 3, q = f & 7;
            int gr = rb + row; if (gr >= R) gr = R - 1;
            va[j] = *(const float4*)&A[(size_t)gr*K + k0 + q*4];
        }
#pragma unroll
        for (int j = 0; j < 4; j++){
            int f = tid + j*256, row = f >> 3, q = f & 7;
            vw[j] = *(const float4*)&W[(size_t)(ob + row)*K + k0 + q*4];
        }
    };
    auto store_chunk = [&](int st){
        char* base = smem + st*STAGE_B;
#pragma unroll
        for (int j = 0; j < 2; j++){
            int f = tid + j*256;
            uint32_t off = (uint32_t)((f>>3)*64 + (f&7)*8);
            off ^= (off >> 3) & 0x30u;
            uint32_t x1,x2,x3, y1,y2,y3, z1,z2,z3, u1,u2,u3;
            split3(va[j].x, x1,x2,x3); split3(va[j].y, y1,y2,y3);
            split3(va[j].z, z1,z2,z3); split3(va[j].w, u1,u2,u3);
            *(uint2*)(base + 0*TILE_A + off) = make_uint2(x1|(y1<<16), z1|(u1<<16));
            *(uint2*)(base + 1*TILE_A + off) = make_uint2(x2|(y2<<16), z2|(u2<<16));
            *(uint2*)(base + 2*TILE_A + off) = make_uint2(x3|(y3<<16), z3|(u3<<16));
        }
        char* wb = base + 3*TILE_A;
#pragma unroll
        for (int j = 0; j < 4; j++){
            int f = tid + j*256;
            uint32_t off = (uint32_t)((f>>3)*64 + (f&7)*8);
            off ^= (off >> 3) & 0x30u;
            uint32_t x1,x2,x3, y1,y2,y3, z1,z2,z3, u1,u2,u3;
            split3(vw[j].x, x1,x2,x3); split3(vw[j].y, y1,y2,y3);
            split3(vw[j].z, z1,z2,z3); split3(vw[j].w, u1,u2,u3);
            *(uint2*)(wb + 0*TILE_W + off) = make_uint2(x1|(y1<<16), z1|(u1<<16));
            *(uint2*)(wb + 1*TILE_W + off) = make_uint2(x2|(y2<<16), z2|(u2<<16));
            *(uint2*)(wb + 2*TILE_W + off) = make_uint2(x3|(y3<<16), z3|(u3<<16));
        }
    };

    load_chunk(0);
    store_chunk(0);
    __syncthreads();

    const int NTc = K / 32;
    const int npair[3] = {3, 2, 1};

    for (int c = 0; c < NTc; c++){
        if (c+1 < NTc) load_chunk((c+1)*32);

        const uint32_t stg = sb + (uint32_t)(c & 1)*STAGE_B;
#pragma unroll
        for (int ks = 0; ks < 2; ks++){
#pragma unroll
            for (int ai = 0; ai < 3; ai++){
                uint32_t afr[2][4];
#pragma unroll
                for (int mt = 0; mt < 2; mt++){
                    uint32_t row = (uint32_t)(wm*32 + mt*16 + (lane & 15));
                    uint32_t off = row*64 + (uint32_t)(ks*32) + (uint32_t)((lane >> 4) << 4);
                    off ^= (off >> 3) & 0x30u;
                    ldm4(afr[mt], stg + ai*TILE_A + off);
                }
#pragma unroll
                for (int wj = 0; wj < 3; wj++){
                    if (wj >= npair[ai]) break;
                    uint32_t bfr[4][2];
#pragma unroll
                    for (int nt2 = 0; nt2 < 2; nt2++){
                        uint32_t row = (uint32_t)(wn*32 + nt2*16 + ((lane >> 4) << 3) + (lane & 7));
                        uint32_t off = row*64 + (uint32_t)(ks*32) + (uint32_t)(((lane >> 3) & 1) << 4);
                        off ^= (off >> 3) & 0x30u;
                        uint32_t r4[4];
                        ldm4(r4, stg + 3*TILE_A + wj*TILE_W + off);
                        bfr[nt2*2][0]=r4[0];   bfr[nt2*2][1]=r4[1];
                        bfr[nt2*2+1][0]=r4[2]; bfr[nt2*2+1][1]=r4[3];
                    }
#pragma unroll
                    for (int mt = 0; mt < 2; mt++)
#pragma unroll
                        for (int nt = 0; nt < 4; nt++)
                            mma16816(acc[mt][nt], afr[mt], bfr[nt]);
                }
            }
        }

        if (c+1 < NTc) store_chunk((c+1) & 1);
        __syncthreads();
    }

    // ---- epilogue: stage via SMEM (stride 129) then coalesced global write --
    float* Cs = (float*)smem;
    {
        const int r0 = wm*32 + (lane >> 2);
        const int c0 = wn*32 + 2*(lane & 3);
#pragma unroll
        for (int mt = 0; mt < 2; mt++)
#pragma unroll
            for (int nt = 0; nt < 4; nt++){
                int row = r0 + mt*16, col = c0 + nt*8;
                Cs[row*129 + col]       = acc[mt][nt][0];
                Cs[row*129 + col + 1]   = acc[mt][nt][1];
                Cs[(row+8)*129 + col]   = acc[mt][nt][2];
                Cs[(row+8)*129 + col+1] = acc[mt][nt][3];
            }
    }
    __syncthreads();

    for (int idx = tid; idx < 64*128; idx += 256){
        int row = idx >> 7, c = idx & 127;
        int r = rb + row;
        if (r < R){
            float v = Cs[row*129 + c] + bias[ob + c];
            size_t g = (size_t)r*O + ob + c;
            if (RES) v += res[g];
            C[g] = v;
        }
    }
}

// ---------------- attention: block per (qchunk, head, batch) ----------------
// 28 query rows per block, streaming softmax over 4 tiles of 49 keys.
// AV loop interchanged: V loads hoisted out of the per-row loop.
__global__ void __launch_bounds__(256) attn_kernel()
{
    const int qc = blockIdx.x, h = blockIdx.y, b = blockIdx.z;
    const int r0 = qc*28;
    __shared__ __align__(16) float Qs[28*68];
    __shared__ __align__(16) float Ks[49*68];
    __shared__ __align__(16) float Vs[49*68];
    __shared__ float S[28*52];
    const int tid = threadIdx.x, lane = tid & 31, w = tid >> 5;

    for (int idx=tid; idx<28*64; idx+=256){
        int row = idx>>6, kx = idx&63;
        Qs[row*68+kx] = g_qkv[(size_t)(b*NN + r0+row)*1536 + h*64 + kx];
    }

    const int nrows = (w<4)?4:3;
    float mrun[4], lrun[4], o0[4], o1[4];
#pragma unroll
    for (int rr=0; rr<4; rr++){ mrun[rr]=-1e30f; lrun[rr]=0.f; o0[rr]=0.f; o1[rr]=0.f; }

    for (int t=0;t<4;t++){
        if (t>0) __syncthreads();
        for (int idx=tid; idx<49*64; idx+=256){
            int j = idx>>6, kx = idx&63;
            int nk = t*49 + j;
            size_t base = (size_t)(b*NN + nk)*1536 + h*64 + kx;
            Ks[j*68+kx] = g_qkv[base + 512];
            Vs[j*68+kx] = g_qkv[base + 1024];
        }
        __syncthreads();
        for (int i=tid; i<28*49; i+=256){
            int row = i/49, j = i - row*49;
            const float4* q4 = (const float4*)&Qs[row*68];
            const float4* k4 = (const float4*)&Ks[j*68];
            float acc = 0.f;
#pragma unroll
            for (int kx=0; kx<16; kx++){
                float4 qa = q4[kx], ka = k4[kx];
                acc += qa.x*ka.x + qa.y*ka.y + qa.z*ka.z + qa.w*ka.w;
            }
            S[row*52+j] = acc * 0.125f;
        }
        __syncthreads();
        // per-row softmax update (cheap scalar phase)
#pragma unroll
        for (int rr=0; rr<4; rr++){
            if (rr >= nrows) break;
            int row = w + 8*rr;
            float s0 = (lane<49) ? S[row*52+lane]    : -1e30f;
            float s1 = (lane<17) ? S[row*52+lane+32] : -1e30f;
            float tm = warp_max(fmaxf(s0,s1));
            float mnew = fmaxf(mrun[rr], tm);
            float alpha = __expf(mrun[rr]-mnew);
            float p0 = (lane<49) ? __expf(s0-mnew) : 0.f;
            float p1 = (lane<17) ? __expf(s1-mnew) : 0.f;
            float psum = warp_sum(p0+p1);
            lrun[rr] = lrun[rr]*alpha + psum;
            mrun[rr] = mnew;
            if (lane<49) S[row*52+lane]    = p0;
            if (lane<17) S[row*52+lane+32] = p1;
            o0[rr]*=alpha; o1[rr]*=alpha;
        }
        __syncwarp();
        // AV: V loads hoisted (2 LDS + nrows broadcast LDS per j)
        for (int j=0;j<49;j++){
            float v0 = Vs[j*68+lane];
            float v1 = Vs[j*68+lane+32];
#pragma unroll
            for (int rr=0; rr<4; rr++){
                if (rr >= nrows) break;
                float pj = S[(w + 8*rr)*52 + j];
                o0[rr] += pj * v0;
                o1[rr] += pj * v1;
            }
        }
    }
    for (int rr=0; rr<nrows; rr++){
        int row = w + 8*rr;
        float inv = 1.f/lrun[rr];
        size_t base = (size_t)(b*NN + r0+row)*512 + h*64;
        g_att[base+lane]    = o0[rr]*inv;
        g_att[base+lane+32] = o1[rr]*inv;
    }
}

// ---------------- LayerNorm + GELU(exact) + w2 -> Qp ----------------
__global__ void __launch_bounds__(256) ln_gelu_qp(
    const float* __restrict__ hin, const float* __restrict__ lng,
    const float* __restrict__ lnb, const float* __restrict__ w2,
    const float* __restrict__ b2, float* __restrict__ qp)
{
    const int r = blockIdx.x, tid = threadIdx.x, lane = tid&31, w = tid>>5;
    __shared__ float gs[512];
    __shared__ float red[16];
    float x0 = hin[(size_t)r*512 + tid];
    float x1 = hin[(size_t)r*512 + tid + 256];
    float s  = warp_sum(x0 + x1);
    float sq = warp_sum(x0*x0 + x1*x1);
    if (lane==0){ red[w]=s; red[w+8]=sq; }
    __syncthreads();
    if (tid==0){
        float S=0,Q=0;
#pragma unroll
        for (int i=0;i<8;i++){ S+=red[i]; Q+=red[i+8]; }
        red[0]=S; red[1]=Q;
    }
    __syncthreads();
    float mean = red[0]*(1.f/512.f);
    float var  = red[1]*(1.f/512.f) - mean*mean;
    float rstd = rsqrtf(var + 1e-5f);

    {
        float y0 = (x0-mean)*rstd*lng[tid]     + lnb[tid];
        float y1 = (x1-mean)*rstd*lng[tid+256] + lnb[tid+256];
        gs[tid]     = 0.5f*y0*(1.f+erff(y0*0.70710678118654752f));
        gs[tid+256] = 0.5f*y1*(1.f+erff(y1*0.70710678118654752f));
    }
    __syncthreads();
    for (int m=w; m<MM; m+=8){
        float acc = 0.f;
#pragma unroll
        for (int i=0;i<16;i++){
            int d = lane + 32*i;
            acc += gs[d]*w2[m*512+d];
        }
        acc = warp_sum(acc);
        if (lane==0) qp[r*MM+m] = acc + b2[m];
    }
}

// ---------------- decomposer: abs-topk + normalize + write [B,N,D,M] -------
__global__ void __launch_bounds__(256) decompose_kernel(
    const float* __restrict__ F, const float* __restrict__ tpl,
    const float* __restrict__ qp, const int* __restrict__ kptr,
    float* __restrict__ out)
{
    const int r = blockIdx.x;
    const int tid = threadIdx.x, lane = tid&31, w = tid>>5;
    __shared__ float fs[512];
    __shared__ int hist[8][256];
    __shared__ unsigned int thr_s[MM];
    __shared__ float scale_s[MM];
    __shared__ unsigned int eqmask_s[MM][16];

    fs[tid]     = F[(size_t)r*512 + tid];
    fs[tid+256] = F[(size_t)r*512 + tid + 256];
    __syncthreads();

    const int kval = *kptr;   // 51

    for (int m=w; m<MM; m+=8){
        float p[16]; unsigned int u[16];
#pragma unroll
        for (int i=0;i<16;i++){
            int d = lane + 32*i;
            p[i] = fs[d]*tpl[m*512+d];
            u[i] = __float_as_uint(fabsf(p[i]));
        }
        unsigned int pref=0u, pmask=0u; int kk = kval;
        const int shifts[4]  = {23,15,7,0};
        const unsigned int dmasks[4] = {0xFFu,0xFFu,0xFFu,0x7Fu};
#pragma unroll
        for (int ps=0; ps<4; ps++){
            const int sh = shifts[ps]; const unsigned int dm = dmasks[ps];
            for (int bI=lane; bI<256; bI+=32) hist[w][bI]=0;
            __syncwarp();
#pragma unroll
            for (int i=0;i<16;i++){
                if ((u[i] & pmask) == pref)
                    atomicAdd(&hist[w][(u[i]>>sh)&dm], 1);
            }
            __syncwarp();
            int base = 255 - 8*lane;
            int s8 = 0;
#pragma unroll
            for (int j=0;j<8;j++) s8 += hist[w][base-j];
            int incl = s8;
#pragma unroll
            for (int off=1; off<32; off<<=1){
                int v = __shfl_up_sync(0xffffffffu, incl, off);
                if (lane>=off) incl += v;
            }
            int excl = incl - s8;
            int dig = -1, kk2 = 0;
            if (excl < kk && incl >= kk){
                int run = excl;
#pragma unroll
                for (int j=0;j<8;j++){
                    int hc = hist[w][base-j];
                    if (dig<0 && run+hc >= kk){ dig = base-j; kk2 = kk-run; }
                    run += hc;
                }
            }
            unsigned int bal = __ballot_sync(0xffffffffu, dig>=0);
            int src = __ffs(bal)-1;
            dig = __shfl_sync(0xffffffffu, dig, src);
            kk  = __shfl_sync(0xffffffffu, kk2, src);
            pref  |= ((unsigned int)dig) << sh;
            pmask |= dm << sh;
            __syncwarp();
        }
        const unsigned int thr = pref;
        const int needeq = kk;

        if (lane<16) eqmask_s[m][lane]=0u;
        __syncwarp();
        float ss = 0.f; int eqbase = 0;
#pragma unroll
        for (int i=0;i<16;i++){
            bool eq = (u[i]==thr);
            unsigned int eb = __ballot_sync(0xffffffffu, eq);
            bool esel = eq && (eqbase + __popc(eb & ((1u<<lane)-1u)) < needeq);
            eqbase += __popc(eb);
            unsigned int sb2 = __ballot_sync(0xffffffffu, esel);
            if (lane==0) eqmask_s[m][i] = sb2;
            if (u[i] > thr || esel) ss += p[i]*p[i];
        }
        ss = warp_sum(ss);
        if (lane==0){
            float q = qp[r*MM+m];
            float nrm = fabsf(q)*sqrtf(ss);
            scale_s[m] = q / fmaxf(nrm, 1e-6f);
            thr_s[m]   = thr;
        }
    }
    __syncthreads();

    const size_t obase = (size_t)r * (512*MM);
    for (int lin=tid; lin<512*MM; lin+=256){
        int d = lin / MM, m = lin - d*MM;
        float pv = fs[d]*tpl[m*512+d];
        unsigned int uu = __float_as_uint(fabsf(pv));
        unsigned int thr = thr_s[m];
        bool sel = (uu > thr) ||
                   (uu == thr && ((eqmask_s[m][d>>5] >> (d&31)) & 1u));
        out[obase + lin] = sel ? pv*scale_s[m] : 0.f;
    }
}

// ---------------- launch ----------------
extern "C" void kernel_launch(void* const* d_in, const int* in_sizes, int n_in,
                              void* d_out, int out_size)
{
    (void)in_sizes; (void)n_in; (void)out_size;
    const float* F     = (const float*)d_in[0];
    const float* in_w  = (const float*)d_in[1];
    const float* in_b  = (const float*)d_in[2];
    const float* out_w = (const float*)d_in[3];
    const float* out_b = (const float*)d_in[4];
    const float* w1    = (const float*)d_in[5];
    const float* b1    = (const float*)d_in[6];
    const float* ln_g  = (const float*)d_in[7];
    const float* ln_b  = (const float*)d_in[8];
    const float* w2    = (const float*)d_in[9];
    const float* b2    = (const float*)d_in[10];
    const float* tpl   = (const float*)d_in[11];
    const int*   kptr  = (const int*)d_in[12];
    float* out = (float*)d_out;

    void *p_qkv, *p_att, *p_enh, *p_h, *p_qp;
    cudaGetSymbolAddress(&p_qkv, g_qkv);
    cudaGetSymbolAddress(&p_att, g_att);
    cudaGetSymbolAddress(&p_enh, g_enh);
    cudaGetSymbolAddress(&p_h,   g_h);
    cudaGetSymbolAddress(&p_qp,  g_qp);
    float* qkv = (float*)p_qkv;
    float* att = (float*)p_att;
    float* enh = (float*)p_enh;
    float* hb  = (float*)p_h;
    float* qp  = (float*)p_qp;

    cudaFuncSetAttribute((const void*)gemm_mma<false>,
                         cudaFuncAttributeMaxDynamicSharedMemorySize, GSM_SIZE);
    cudaFuncSetAttribute((const void*)gemm_mma<true>,
                         cudaFuncAttributeMaxDynamicSharedMemorySize, GSM_SIZE);

    const int gy = (RTOT + 63) / 64;   // 49

    // 1) qkv = F @ in_proj_w^T + b        [3136,1536]
    gemm_mma<false><<<dim3(1536/128, gy), 256, GSM_SIZE>>>(F, in_w, in_b, nullptr, qkv, RTOT, 512, 1536);
    // 2) attention -> g_att
    attn_kernel<<<dim3(7, HH, BB), 256>>>();
    // 3) F_enh = att @ out_w^T + out_b + F
    gemm_mma<true><<<dim3(512/128, gy), 256, GSM_SIZE>>>(att, out_w, out_b, F, enh, RTOT, 512, 512);
    // 4) h = F_enh @ w1^T + b1
    gemm_mma<false><<<dim3(512/128, gy), 256, GSM_SIZE>>>(enh, w1, b1, nullptr, hb, RTOT, 512, 512);
    // 5) LN + GELU + w2 -> Qp
    ln_gelu_qp<<<RTOT, 256>>>(hb, ln_g, ln_b, w2, b2, qp);
    // 6) decompose: topk + normalize + write [B,N,D,M]
    decompose_kernel<<<RTOT, 256>>>(F, tpl, qp, kptr, out);
}

// round 7
// speedup vs baseline: 1.5065x; 1.0140x over previous
#include <cuda_runtime.h>
#include <cuda_bf16.h>
#include <math.h>
#include <stdint.h>

#define BB 16
#define NN 196
#define DD 512
#define MM 20
#define HH 8
#define HD 64
#define RTOT (BB*NN)   /* 3136 */
#define WROWS 2560     /* in_w 1536 + out_w 512 + w1 512 */

// ---------------- scratch (device globals; no allocation) ----------------
__device__ float g_qkv[RTOT*3*DD];
__device__ float g_att[RTOT*DD];
__device__ float g_enh[RTOT*DD];
__device__ float g_h[RTOT*DD];
__device__ float g_qp[RTOT*MM];
__device__ __nv_bfloat16 g_A1[RTOT*DD], g_A2[RTOT*DD], g_A3[RTOT*DD];
__device__ __nv_bfloat16 g_W1[WROWS*DD], g_W2[WROWS*DD], g_W3[WROWS*DD];

// ---------------- warp helpers ----------------
__device__ __forceinline__ float warp_sum(float v){
#pragma unroll
    for (int off=16; off; off>>=1) v += __shfl_xor_sync(0xffffffffu, v, off);
    return v;
}
__device__ __forceinline__ float warp_max(float v){
#pragma unroll
    for (int off=16; off; off>>=1) v = fmaxf(v, __shfl_xor_sync(0xffffffffu, v, off));
    return v;
}

// ---------------- mma.sync / cp.async helpers ----------------
__device__ __forceinline__ uint32_t smem_u32(const void* p){
    uint32_t a;
    asm("{ .reg .u64 t; cvta.to.shared.u64 t, %1; cvt.u32.u64 %0, t; }" : "=r"(a) : "l"(p));
    return a;
}
__device__ __forceinline__ void ldm4(uint32_t* r, uint32_t addr){
    asm volatile("ldmatrix.sync.aligned.m8n8.x4.shared.b16 {%0,%1,%2,%3}, [%4];"
        : "=r"(r[0]),"=r"(r[1]),"=r"(r[2]),"=r"(r[3]) : "r"(addr));
}
__device__ __forceinline__ void mma16816(float* c, const uint32_t* a, const uint32_t* b){
    asm volatile("mma.sync.aligned.m16n8k16.row.col.f32.bf16.bf16.f32 "
        "{%0,%1,%2,%3}, {%4,%5,%6,%7}, {%8,%9}, {%0,%1,%2,%3};"
        : "+f"(c[0]),"+f"(c[1]),"+f"(c[2]),"+f"(c[3])
        : "r"(a[0]),"r"(a[1]),"r"(a[2]),"r"(a[3]), "r"(b[0]),"r"(b[1]));
}
__device__ __forceinline__ void cp16(uint32_t dst, const void* src){
    uint64_t g = __cvta_generic_to_global(src);
    asm volatile("cp.async.ca.shared.global [%0], [%1], 16;" :: "r"(dst), "l"(g) : "memory");
}

// 3-way bf16 cascade split: v = h1 + h2 + h3 + O(2^-27 |v|)
__device__ __forceinline__ void split3(float v, uint32_t& t1, uint32_t& t2, uint32_t& t3){
    __nv_bfloat16 h1 = __float2bfloat16_rn(v);
    float r1 = v - __bfloat162float(h1);
    __nv_bfloat16 h2 = __float2bfloat16_rn(r1);
    float r2 = r1 - __bfloat162float(h2);
    __nv_bfloat16 h3 = __float2bfloat16_rn(r2);
    t1 = (uint32_t)__bfloat16_as_ushort(h1);
    t2 = (uint32_t)__bfloat16_as_ushort(h2);
    t3 = (uint32_t)__bfloat16_as_ushort(h3);
}

// ---------------- pre-split: fp32 matrix -> 3 bf16 matrices -----------------
__global__ void __launch_bounds__(256) split_mat(
    const float* __restrict__ X,
    __nv_bfloat16* __restrict__ o1, __nv_bfloat16* __restrict__ o2,
    __nv_bfloat16* __restrict__ o3, int n4)
{
    int i = blockIdx.x*256 + threadIdx.x;
    if (i >= n4) return;
    float4 v = *(const float4*)&X[(size_t)i*4];
    uint32_t x1,x2,x3, y1,y2,y3, z1,z2,z3, u1,u2,u3;
    split3(v.x, x1,x2,x3); split3(v.y, y1,y2,y3);
    split3(v.z, z1,z2,z3); split3(v.w, u1,u2,u3);
    *(uint2*)&o1[(size_t)i*4] = make_uint2(x1|(y1<<16), z1|(u1<<16));
    *(uint2*)&o2[(size_t)i*4] = make_uint2(x2|(y2<<16), z2|(u2<<16));
    *(uint2*)&o3[(size_t)i*4] = make_uint2(x3|(y3<<16), z3|(u3<<16));
}

// ---------------- pure-bf16 tensor-core GEMM --------------------------------
// C[r][o] = sum_k A[r][k]*W[o][k] + bias[o] (+res); A,W pre-split to 3 terms.
// 64x128 tile/CTA, 8 warps (2m x 4n), warp tile 32x32. cp.async double buffer.
// ----------------------------------------------------------------------------
#define TILE_A   4096                 /* 64 rows x 32 bf16 x 2B */
#define TILE_W   8192                 /* 128 rows x 32 bf16 x 2B */
#define STAGE_B  (3*TILE_A + 3*TILE_W)   /* 36864 */
#define GSM_SIZE (2*STAGE_B)             /* 73728 */

template<bool RES>
__global__ void __launch_bounds__(256) gemm_bf(
    const __nv_bfloat16* __restrict__ A1, const __nv_bfloat16* __restrict__ A2,
    const __nv_bfloat16* __restrict__ A3,
    const __nv_bfloat16* __restrict__ W1, const __nv_bfloat16* __restrict__ W2,
    const __nv_bfloat16* __restrict__ W3,
    const float* __restrict__ bias, const float* __restrict__ res,
    float* __restrict__ C, int R, int K, int O)
{
    extern __shared__ __align__(128) char smem[];
    const uint32_t sb = smem_u32(smem);
    const int tid = threadIdx.x, lane = tid & 31, wid = tid >> 5;
    const int rb = blockIdx.y * 64, ob = blockIdx.x * 128;
    const int wm = wid & 1, wn = wid >> 1;

    float acc[2][4][4];
#pragma unroll
    for (int i=0;i<2;i++)
#pragma unroll
        for (int j=0;j<4;j++)
#pragma unroll
            for (int q=0;q<4;q++) acc[i][j][q]=0.f;

    const __nv_bfloat16* As[3] = {A1, A2, A3};
    const __nv_bfloat16* Ws[3] = {W1, W2, W3};

    // per-thread fixed coordinates for the async copies
    const int ar = tid >> 2, aq = tid & 3;            // A: row 0..63, seg 0..3
    int gra = rb + ar; if (gra >= R) gra = R - 1;
    uint32_t aoffsw = (uint32_t)(ar*64 + aq*16); aoffsw ^= (aoffsw>>3) & 0x30u;

    auto issue_chunk = [&](int c){
        const uint32_t base = sb + (uint32_t)(c & 1)*STAGE_B;
        const int k0 = c*32;
#pragma unroll
        for (int t = 0; t < 3; t++)
            cp16(base + t*TILE_A + aoffsw, As[t] + (size_t)gra*K + k0 + aq*8);
#pragma unroll
        for (int j = 0; j < 6; j++){
            int wi = j >> 1;
            int r  = (j & 1)*64 + (tid >> 2);
            int q  = tid & 3;
            uint32_t off = (uint32_t)(r*64 + q*16); off ^= (off>>3) & 0x30u;
            cp16(base + 3*TILE_A + wi*TILE_W + off, Ws[wi] + (size_t)(ob + r)*K + k0 + q*8);
        }
        asm volatile("cp.async.commit_group;" ::: "memory");
    };

    issue_chunk(0);

    const int NTc = K / 32;
    const int npair[3] = {3, 2, 1};

    for (int c = 0; c < NTc; c++){
        if (c+1 < NTc){
            issue_chunk(c+1);
            asm volatile("cp.async.wait_group 1;" ::: "memory");
        } else {
            asm volatile("cp.async.wait_group 0;" ::: "memory");
        }
        __syncthreads();

        const uint32_t stg = sb + (uint32_t)(c & 1)*STAGE_B;
#pragma unroll
        for (int ks = 0; ks < 2; ks++){
#pragma unroll
            for (int ai = 0; ai < 3; ai++){
                uint32_t afr[2][4];
#pragma unroll
                for (int mt = 0; mt < 2; mt++){
                    uint32_t row = (uint32_t)(wm*32 + mt*16 + (lane & 15));
                    uint32_t off = row*64 + (uint32_t)(ks*32) + (uint32_t)((lane >> 4) << 4);
                    off ^= (off >> 3) & 0x30u;
                    ldm4(afr[mt], stg + ai*TILE_A + off);
                }
#pragma unroll
                for (int wj = 0; wj < 3; wj++){
                    if (wj >= npair[ai]) break;
                    uint32_t bfr[4][2];
#pragma unroll
                    for (int nt2 = 0; nt2 < 2; nt2++){
                        uint32_t row = (uint32_t)(wn*32 + nt2*16 + ((lane >> 4) << 3) + (lane & 7));
                        uint32_t off = row*64 + (uint32_t)(ks*32) + (uint32_t)(((lane >> 3) & 1) << 4);
                        off ^= (off >> 3) & 0x30u;
                        uint32_t r4[4];
                        ldm4(r4, stg + 3*TILE_A + wj*TILE_W + off);
                        bfr[nt2*2][0]=r4[0];   bfr[nt2*2][1]=r4[1];
                        bfr[nt2*2+1][0]=r4[2]; bfr[nt2*2+1][1]=r4[3];
                    }
#pragma unroll
                    for (int mt = 0; mt < 2; mt++)
#pragma unroll
                        for (int nt = 0; nt < 4; nt++)
                            mma16816(acc[mt][nt], afr[mt], bfr[nt]);
                }
            }
        }
        __syncthreads();
    }

    // ---- epilogue ----
    float* Cs = (float*)smem;
    {
        const int r0 = wm*32 + (lane >> 2);
        const int c0 = wn*32 + 2*(lane & 3);
#pragma unroll
        for (int mt = 0; mt < 2; mt++)
#pragma unroll
            for (int nt = 0; nt < 4; nt++){
                int row = r0 + mt*16, col = c0 + nt*8;
                Cs[row*129 + col]       = acc[mt][nt][0];
                Cs[row*129 + col + 1]   = acc[mt][nt][1];
                Cs[(row+8)*129 + col]   = acc[mt][nt][2];
                Cs[(row+8)*129 + col+1] = acc[mt][nt][3];
            }
    }
    __syncthreads();

    for (int idx = tid; idx < 64*128; idx += 256){
        int row = idx >> 7, c = idx & 127;
        int r = rb + row;
        if (r < R){
            float v = Cs[row*129 + c] + bias[ob + c];
            size_t g = (size_t)r*O + ob + c;
            if (RES) v += res[g];
            C[g] = v;
        }
    }
}

// ---------------- attention ----------------
__global__ void __launch_bounds__(256) attn_kernel()
{
    const int qc = blockIdx.x, h = blockIdx.y, b = blockIdx.z;
    const int r0 = qc*28;
    __shared__ __align__(16) float Qs[28*68];
    __shared__ __align__(16) float Ks[49*68];
    __shared__ __align__(16) float Vs[49*68];
    __shared__ float S[28*52];
    const int tid = threadIdx.x, lane = tid & 31, w = tid >> 5;

    for (int idx=tid; idx<28*64; idx+=256){
        int row = idx>>6, kx = idx&63;
        Qs[row*68+kx] = g_qkv[(size_t)(b*NN + r0+row)*1536 + h*64 + kx];
    }

    const int nrows = (w<4)?4:3;
    float mrun[4], lrun[4], o0[4], o1[4];
#pragma unroll
    for (int rr=0; rr<4; rr++){ mrun[rr]=-1e30f; lrun[rr]=0.f; o0[rr]=0.f; o1[rr]=0.f; }

    const int srow = tid >> 3, jg = tid & 7;   // score-phase mapping

    for (int t=0;t<4;t++){
        if (t>0) __syncthreads();
        for (int idx=tid; idx<49*64; idx+=256){
            int j = idx>>6, kx = idx&63;
            int nk = t*49 + j;
            size_t base = (size_t)(b*NN + nk)*1536 + h*64 + kx;
            Ks[j*68+kx] = g_qkv[base + 512];
            Vs[j*68+kx] = g_qkv[base + 1024];
        }
        __syncthreads();
        // scores: thread -> (srow, j = jg + 8*jj), Q fragment reused across j
        if (srow < 28){
            float acc[7];
#pragma unroll
            for (int jj=0;jj<7;jj++) acc[jj]=0.f;
            const float4* q4 = (const float4*)&Qs[srow*68];
#pragma unroll
            for (int kx=0; kx<16; kx++){
                float4 qa = q4[kx];
#pragma unroll
                for (int jj=0;jj<7;jj++){
                    int j = jg + 8*jj;
                    if (j < 49){
                        float4 ka = *(const float4*)&Ks[j*68 + kx*4];
                        acc[jj] += qa.x*ka.x + qa.y*ka.y + qa.z*ka.z + qa.w*ka.w;
                    }
                }
            }
#pragma unroll
            for (int jj=0;jj<7;jj++){
                int j = jg + 8*jj;
                if (j < 49) S[srow*52+j] = acc[jj]*0.125f;
            }
        }
        __syncthreads();
        // per-row softmax update
#pragma unroll
        for (int rr=0; rr<4; rr++){
            if (rr >= nrows) break;
            int row = w + 8*rr;
            float s0 = (lane<49) ? S[row*52+lane]    : -1e30f;
            float s1 = (lane<17) ? S[row*52+lane+32] : -1e30f;
            float tm = warp_max(fmaxf(s0,s1));
            float mnew = fmaxf(mrun[rr], tm);
            float alpha = __expf(mrun[rr]-mnew);
            float p0 = (lane<49) ? __expf(s0-mnew) : 0.f;
            float p1 = (lane<17) ? __expf(s1-mnew) : 0.f;
            float psum = warp_sum(p0+p1);
            lrun[rr] = lrun[rr]*alpha + psum;
            mrun[rr] = mnew;
            if (lane<49) S[row*52+lane]    = p0;
            if (lane<17) S[row*52+lane+32] = p1;
            o0[rr]*=alpha; o1[rr]*=alpha;
        }
        __syncwarp();
        // AV: hoisted V loads
        for (int j=0;j<49;j++){
            float v0 = Vs[j*68+lane];
            float v1 = Vs[j*68+lane+32];
#pragma unroll
            for (int rr=0; rr<4; rr++){
                if (rr >= nrows) break;
                float pj = S[(w + 8*rr)*52 + j];
                o0[rr] += pj * v0;
                o1[rr] += pj * v1;
            }
        }
    }
    for (int rr=0; rr<nrows; rr++){
        int row = w + 8*rr;
        float inv = 1.f/lrun[rr];
        size_t base = (size_t)(b*NN + r0+row)*512 + h*64;
        g_att[base+lane]    = o0[rr]*inv;
        g_att[base+lane+32] = o1[rr]*inv;
    }
}

// ---------------- LayerNorm + GELU(exact) + w2 -> Qp ----------------
__global__ void __launch_bounds__(256) ln_gelu_qp(
    const float* __restrict__ hin, const float* __restrict__ lng,
    const float* __restrict__ lnb, const float* __restrict__ w2,
    const float* __restrict__ b2, float* __restrict__ qp)
{
    const int r = blockIdx.x, tid = threadIdx.x, lane = tid&31, w = tid>>5;
    __shared__ float gs[512];
    __shared__ float red[16];
    float x0 = hin[(size_t)r*512 + tid];
    float x1 = hin[(size_t)r*512 + tid + 256];
    float s  = warp_sum(x0 + x1);
    float sq = warp_sum(x0*x0 + x1*x1);
    if (lane==0){ red[w]=s; red[w+8]=sq; }
    __syncthreads();
    if (tid==0){
        float S=0,Q=0;
#pragma unroll
        for (int i=0;i<8;i++){ S+=red[i]; Q+=red[i+8]; }
        red[0]=S; red[1]=Q;
    }
    __syncthreads();
    float mean = red[0]*(1.f/512.f);
    float var  = red[1]*(1.f/512.f) - mean*mean;
    float rstd = rsqrtf(var + 1e-5f);

    {
        float y0 = (x0-mean)*rstd*lng[tid]     + lnb[tid];
        float y1 = (x1-mean)*rstd*lng[tid+256] + lnb[tid+256];
        gs[tid]     = 0.5f*y0*(1.f+erff(y0*0.70710678118654752f));
        gs[tid+256] = 0.5f*y1*(1.f+erff(y1*0.70710678118654752f));
    }
    __syncthreads();
    for (int m=w; m<MM; m+=8){
        float acc = 0.f;
#pragma unroll
        for (int i=0;i<16;i++){
            int d = lane + 32*i;
            acc += gs[d]*w2[m*512+d];
        }
        acc = warp_sum(acc);
        if (lane==0) qp[r*MM+m] = acc + b2[m];
    }
}

// ---------------- decomposer ----------------
__global__ void __launch_bounds__(256) decompose_kernel(
    const float* __restrict__ F, const float* __restrict__ tpl,
    const float* __restrict__ qp, const int* __restrict__ kptr,
    float* __restrict__ out)
{
    const int r = blockIdx.x;
    const int tid = threadIdx.x, lane = tid&31, w = tid>>5;
    __shared__ float fs[512];
    __shared__ int hist[8][256];
    __shared__ unsigned int thr_s[MM];
    __shared__ float scale_s[MM];
    __shared__ unsigned int eqmask_s[MM][16];

    fs[tid]     = F[(size_t)r*512 + tid];
    fs[tid+256] = F[(size_t)r*512 + tid + 256];
    __syncthreads();

    const int kval = *kptr;   // 51

    for (int m=w; m<MM; m+=8){
        float p[16]; unsigned int u[16];
#pragma unroll
        for (int i=0;i<16;i++){
            int d = lane + 32*i;
            p[i] = fs[d]*tpl[m*512+d];
            u[i] = __float_as_uint(fabsf(p[i]));
        }
        unsigned int pref=0u, pmask=0u; int kk = kval;
        const int shifts[4]  = {23,15,7,0};
        const unsigned int dmasks[4] = {0xFFu,0xFFu,0xFFu,0x7Fu};
#pragma unroll
        for (int ps=0; ps<4; ps++){
            const int sh = shifts[ps]; const unsigned int dm = dmasks[ps];
            for (int bI=lane; bI<256; bI+=32) hist[w][bI]=0;
            __syncwarp();
#pragma unroll
            for (int i=0;i<16;i++){
                if ((u[i] & pmask) == pref)
                    atomicAdd(&hist[w][(u[i]>>sh)&dm], 1);
            }
            __syncwarp();
            int base = 255 - 8*lane;
            int s8 = 0;
#pragma unroll
            for (int j=0;j<8;j++) s8 += hist[w][base-j];
            int incl = s8;
#pragma unroll
            for (int off=1; off<32; off<<=1){
                int v = __shfl_up_sync(0xffffffffu, incl, off);
                if (lane>=off) incl += v;
            }
            int excl = incl - s8;
            int dig = -1, kk2 = 0;
            if (excl < kk && incl >= kk){
                int run = excl;
#pragma unroll
                for (int j=0;j<8;j++){
                    int hc = hist[w][base-j];
                    if (dig<0 && run+hc >= kk){ dig = base-j; kk2 = kk-run; }
                    run += hc;
                }
            }
            unsigned int bal = __ballot_sync(0xffffffffu, dig>=0);
            int src = __ffs(bal)-1;
            dig = __shfl_sync(0xffffffffu, dig, src);
            kk  = __shfl_sync(0xffffffffu, kk2, src);
            pref  |= ((unsigned int)dig) << sh;
            pmask |= dm << sh;
            __syncwarp();
        }
        const unsigned int thr = pref;
        const int needeq = kk;

        if (lane<16) eqmask_s[m][lane]=0u;
        __syncwarp();
        float ss = 0.f; int eqbase = 0;
#pragma unroll
        for (int i=0;i<16;i++){
            bool eq = (u[i]==thr);
            unsigned int eb = __ballot_sync(0xffffffffu, eq);
            bool esel = eq && (eqbase + __popc(eb & ((1u<<lane)-1u)) < needeq);
            eqbase += __popc(eb);
            unsigned int sb2 = __ballot_sync(0xffffffffu, esel);
            if (lane==0) eqmask_s[m][i] = sb2;
            if (u[i] > thr || esel) ss += p[i]*p[i];
        }
        ss = warp_sum(ss);
        if (lane==0){
            float q = qp[r*MM+m];
            float nrm = fabsf(q)*sqrtf(ss);
            scale_s[m] = q / fmaxf(nrm, 1e-6f);
            thr_s[m]   = thr;
        }
    }
    __syncthreads();

    const size_t obase = (size_t)r * (512*MM);
    for (int lin=tid; lin<512*MM; lin+=256){
        int d = lin / MM, m = lin - d*MM;
        float pv = fs[d]*tpl[m*512+d];
        unsigned int uu = __float_as_uint(fabsf(pv));
        unsigned int thr = thr_s[m];
        bool sel = (uu > thr) ||
                   (uu == thr && ((eqmask_s[m][d>>5] >> (d&31)) & 1u));
        out[obase + lin] = sel ? pv*scale_s[m] : 0.f;
    }
}

// ---------------- launch ----------------
extern "C" void kernel_launch(void* const* d_in, const int* in_sizes, int n_in,
                              void* d_out, int out_size)
{
    (void)in_sizes; (void)n_in; (void)out_size;
    const float* F     = (const float*)d_in[0];
    const float* in_w  = (const float*)d_in[1];
    const float* in_b  = (const float*)d_in[2];
    const float* out_w = (const float*)d_in[3];
    const float* out_b = (const float*)d_in[4];
    const float* w1    = (const float*)d_in[5];
    const float* b1    = (const float*)d_in[6];
    const float* ln_g  = (const float*)d_in[7];
    const float* ln_b  = (const float*)d_in[8];
    const float* w2    = (const float*)d_in[9];
    const float* b2    = (const float*)d_in[10];
    const float* tpl   = (const float*)d_in[11];
    const int*   kptr  = (const int*)d_in[12];
    float* out = (float*)d_out;

    void *p_qkv, *p_att, *p_enh, *p_h, *p_qp;
    void *pA1, *pA2, *pA3, *pW1, *pW2, *pW3;
    cudaGetSymbolAddress(&p_qkv, g_qkv);
    cudaGetSymbolAddress(&p_att, g_att);
    cudaGetSymbolAddress(&p_enh, g_enh);
    cudaGetSymbolAddress(&p_h,   g_h);
    cudaGetSymbolAddress(&p_qp,  g_qp);
    cudaGetSymbolAddress(&pA1, g_A1); cudaGetSymbolAddress(&pA2, g_A2);
    cudaGetSymbolAddress(&pA3, g_A3); cudaGetSymbolAddress(&pW1, g_W1);
    cudaGetSymbolAddress(&pW2, g_W2); cudaGetSymbolAddress(&pW3, g_W3);
    float* qkv = (float*)p_qkv;
    float* att = (float*)p_att;
    float* enh = (float*)p_enh;
    float* hb  = (float*)p_h;
    float* qp  = (float*)p_qp;
    __nv_bfloat16 *A1=(__nv_bfloat16*)pA1, *A2=(__nv_bfloat16*)pA2, *A3=(__nv_bfloat16*)pA3;
    __nv_bfloat16 *W1=(__nv_bfloat16*)pW1, *W2=(__nv_bfloat16*)pW2, *W3=(__nv_bfloat16*)pW3;

    cudaFuncSetAttribute((const void*)gemm_bf<false>,
                         cudaFuncAttributeMaxDynamicSharedMemorySize, GSM_SIZE);
    cudaFuncSetAttribute((const void*)gemm_bf<true>,
                         cudaFuncAttributeMaxDynamicSharedMemorySize, GSM_SIZE);

    const int gy = (RTOT + 63) / 64;   // 49
    const int nA4 = RTOT*DD/4;         // float4 count for activations

    // weight splits (in_w @0, out_w @1536*512, w1 @2048*512)
    split_mat<<<(1536*DD/4 + 255)/256, 256>>>(in_w,  W1, W2, W3, 1536*DD/4);
    split_mat<<<(512*DD/4 + 255)/256, 256>>>(out_w, W1+1536*DD, W2+1536*DD, W3+1536*DD, 512*DD/4);
    split_mat<<<(512*DD/4 + 255)/256, 256>>>(w1,    W1+2048*DD, W2+2048*DD, W3+2048*DD, 512*DD/4);

    // 1) qkv
    split_mat<<<(nA4 + 255)/256, 256>>>(F, A1, A2, A3, nA4);
    gemm_bf<false><<<dim3(1536/128, gy), 256, GSM_SIZE>>>(A1, A2, A3, W1, W2, W3,
                                                          in_b, nullptr, qkv, RTOT, DD, 1536);
    // 2) attention
    attn_kernel<<<dim3(7, HH, BB), 256>>>();
    // 3) F_enh = att @ out_w^T + out_b + F
    split_mat<<<(nA4 + 255)/256, 256>>>(att, A1, A2, A3, nA4);
    gemm_bf<true><<<dim3(512/128, gy), 256, GSM_SIZE>>>(A1, A2, A3,
        W1+1536*DD, W2+1536*DD, W3+1536*DD, out_b, F, enh, RTOT, DD, 512);
    // 4) h = F_enh @ w1^T + b1
    split_mat<<<(nA4 + 255)/256, 256>>>(enh, A1, A2, A3, nA4);
    gemm_bf<false><<<dim3(512/128, gy), 256, GSM_SIZE>>>(A1, A2, A3,
        W1+2048*DD, W2+2048*DD, W3+2048*DD, b1, nullptr, hb, RTOT, DD, 512);
    // 5) LN + GELU + w2 -> Qp
    ln_gelu_qp<<<RTOT, 256>>>(hb, ln_g, ln_b, w2, b2, qp);
    // 6) decompose
    decompose_kernel<<<RTOT, 256>>>(F, tpl, qp, kptr, out);
}

// round 8
// speedup vs baseline: 1.5110x; 1.0030x over previous
#include <cuda_runtime.h>
#include <cuda_bf16.h>
#include <math.h>
#include <stdint.h>

#define BB 16
#define NN 196
#define DD 512
#define MM 20
#define HH 8
#define HD 64
#define RTOT (BB*NN)   /* 3136 */
#define WROWS 2560     /* in_w 1536 + out_w 512 + w1 512 */

// ---------------- scratch (device globals; no allocation) ----------------
__device__ float g_qkv[RTOT*3*DD];
__device__ float g_h[RTOT*DD];
__device__ __nv_bfloat16 g_A1[RTOT*DD], g_A2[RTOT*DD], g_A3[RTOT*DD];
__device__ __nv_bfloat16 g_B1[RTOT*DD], g_B2[RTOT*DD], g_B3[RTOT*DD];
__device__ __nv_bfloat16 g_W1[WROWS*DD], g_W2[WROWS*DD], g_W3[WROWS*DD];

// ---------------- warp helpers ----------------
__device__ __forceinline__ float warp_sum(float v){
#pragma unroll
    for (int off=16; off; off>>=1) v += __shfl_xor_sync(0xffffffffu, v, off);
    return v;
}
__device__ __forceinline__ float warp_max(float v){
#pragma unroll
    for (int off=16; off; off>>=1) v = fmaxf(v, __shfl_xor_sync(0xffffffffu, v, off));
    return v;
}

// ---------------- mma.sync / cp.async helpers ----------------
__device__ __forceinline__ uint32_t smem_u32(const void* p){
    uint32_t a;
    asm("{ .reg .u64 t; cvta.to.shared.u64 t, %1; cvt.u32.u64 %0, t; }" : "=r"(a) : "l"(p));
    return a;
}
__device__ __forceinline__ void ldm4(uint32_t* r, uint32_t addr){
    asm volatile("ldmatrix.sync.aligned.m8n8.x4.shared.b16 {%0,%1,%2,%3}, [%4];"
        : "=r"(r[0]),"=r"(r[1]),"=r"(r[2]),"=r"(r[3]) : "r"(addr));
}
__device__ __forceinline__ void mma16816(float* c, const uint32_t* a, const uint32_t* b){
    asm volatile("mma.sync.aligned.m16n8k16.row.col.f32.bf16.bf16.f32 "
        "{%0,%1,%2,%3}, {%4,%5,%6,%7}, {%8,%9}, {%0,%1,%2,%3};"
        : "+f"(c[0]),"+f"(c[1]),"+f"(c[2]),"+f"(c[3])
        : "r"(a[0]),"r"(a[1]),"r"(a[2]),"r"(a[3]), "r"(b[0]),"r"(b[1]));
}
__device__ __forceinline__ void cp16(uint32_t dst, const void* src){
    uint64_t g = __cvta_generic_to_global(src);
    asm volatile("cp.async.ca.shared.global [%0], [%1], 16;" :: "r"(dst), "l"(g) : "memory");
}

// 3-way bf16 cascade split: v = h1 + h2 + h3 + O(2^-27 |v|)
__device__ __forceinline__ void split3(float v, uint32_t& t1, uint32_t& t2, uint32_t& t3){
    __nv_bfloat16 h1 = __float2bfloat16_rn(v);
    float r1 = v - __bfloat162float(h1);
    __nv_bfloat16 h2 = __float2bfloat16_rn(r1);
    float r2 = r1 - __bfloat162float(h2);
    __nv_bfloat16 h3 = __float2bfloat16_rn(r2);
    t1 = (uint32_t)__bfloat16_as_ushort(h1);
    t2 = (uint32_t)__bfloat16_as_ushort(h2);
    t3 = (uint32_t)__bfloat16_as_ushort(h3);
}
__device__ __forceinline__ __nv_bfloat16 asbf(uint32_t t){
    return __ushort_as_bfloat16((unsigned short)t);
}

// ---------------- pre-split: fp32 matrix -> 3 bf16 matrices -----------------
__global__ void __launch_bounds__(256) split_mat(
    const float* __restrict__ X,
    __nv_bfloat16* __restrict__ o1, __nv_bfloat16* __restrict__ o2,
    __nv_bfloat16* __restrict__ o3, int n4)
{
    int i = blockIdx.x*256 + threadIdx.x;
    if (i >= n4) return;
    float4 v = *(const float4*)&X[(size_t)i*4];
    uint32_t x1,x2,x3, y1,y2,y3, z1,z2,z3, u1,u2,u3;
    split3(v.x, x1,x2,x3); split3(v.y, y1,y2,y3);
    split3(v.z, z1,z2,z3); split3(v.w, u1,u2,u3);
    *(uint2*)&o1[(size_t)i*4] = make_uint2(x1|(y1<<16), z1|(u1<<16));
    *(uint2*)&o2[(size_t)i*4] = make_uint2(x2|(y2<<16), z2|(u2<<16));
    *(uint2*)&o3[(size_t)i*4] = make_uint2(x3|(y3<<16), z3|(u3<<16));
}

// ---------------- pure-bf16 tensor-core GEMM --------------------------------
// 64x128 tile/CTA, 8 warps (2m x 4n), warp tile 32x32. cp.async double buffer.
// Fragment-reuse mainloop: 12 ldmatrix + 48 mma per k16-step.
// SPLITOUT: write 3-term bf16 split of C into g_B* instead of fp32 C.
// ----------------------------------------------------------------------------
#define TILE_A   4096
#define TILE_W   8192
#define STAGE_B  (3*TILE_A + 3*TILE_W)   /* 36864 */
#define GSM_SIZE (2*STAGE_B)             /* 73728 */

template<bool RES, bool SPLITOUT>
__global__ void __launch_bounds__(256) gemm_bf(
    const __nv_bfloat16* __restrict__ A1, const __nv_bfloat16* __restrict__ A2,
    const __nv_bfloat16* __restrict__ A3,
    const __nv_bfloat16* __restrict__ W1, const __nv_bfloat16* __restrict__ W2,
    const __nv_bfloat16* __restrict__ W3,
    const float* __restrict__ bias, const float* __restrict__ res,
    float* __restrict__ C, int R, int K, int O)
{
    extern __shared__ __align__(128) char smem[];
    const uint32_t sb = smem_u32(smem);
    const int tid = threadIdx.x, lane = tid & 31, wid = tid >> 5;
    const int rb = blockIdx.y * 64, ob = blockIdx.x * 128;
    const int wm = wid & 1, wn = wid >> 1;

    float acc[2][4][4];
#pragma unroll
    for (int i=0;i<2;i++)
#pragma unroll
        for (int j=0;j<4;j++)
#pragma unroll
            for (int q=0;q<4;q++) acc[i][j][q]=0.f;

    const __nv_bfloat16* As[3] = {A1, A2, A3};
    const __nv_bfloat16* Ws[3] = {W1, W2, W3};

    const int ar = tid >> 2, aq = tid & 3;
    int gra = rb + ar; if (gra >= R) gra = R - 1;
    uint32_t aoffsw = (uint32_t)(ar*64 + aq*16); aoffsw ^= (aoffsw>>3) & 0x30u;

    auto issue_chunk = [&](int c){
        const uint32_t base = sb + (uint32_t)(c & 1)*STAGE_B;
        const int k0 = c*32;
#pragma unroll
        for (int t = 0; t < 3; t++)
            cp16(base + t*TILE_A + aoffsw, As[t] + (size_t)gra*K + k0 + aq*8);
#pragma unroll
        for (int j = 0; j < 6; j++){
            int wi = j >> 1;
            int r  = (j & 1)*64 + (tid >> 2);
            int q  = tid & 3;
            uint32_t off = (uint32_t)(r*64 + q*16); off ^= (off>>3) & 0x30u;
            cp16(base + 3*TILE_A + wi*TILE_W + off, Ws[wi] + (size_t)(ob + r)*K + k0 + q*8);
        }
        asm volatile("cp.async.commit_group;" ::: "memory");
    };

    issue_chunk(0);

    const int NTc = K / 32;

    for (int c = 0; c < NTc; c++){
        if (c+1 < NTc){
            issue_chunk(c+1);
            asm volatile("cp.async.wait_group 1;" ::: "memory");
        } else {
            asm volatile("cp.async.wait_group 0;" ::: "memory");
        }
        __syncthreads();

        const uint32_t stg = sb + (uint32_t)(c & 1)*STAGE_B;
#pragma unroll
        for (int ks = 0; ks < 2; ks++){
            // load ALL fragments once
            uint32_t afr[3][2][4];
#pragma unroll
            for (int ai = 0; ai < 3; ai++)
#pragma unroll
                for (int mt = 0; mt < 2; mt++){
                    uint32_t row = (uint32_t)(wm*32 + mt*16 + (lane & 15));
                    uint32_t off = row*64 + (uint32_t)(ks*32) + (uint32_t)((lane >> 4) << 4);
                    off ^= (off >> 3) & 0x30u;
                    ldm4(afr[ai][mt], stg + ai*TILE_A + off);
                }
            uint32_t bfr[3][4][2];
#pragma unroll
            for (int wj = 0; wj < 3; wj++)
#pragma unroll
                for (int nt2 = 0; nt2 < 2; nt2++){
                    uint32_t row = (uint32_t)(wn*32 + nt2*16 + ((lane >> 4) << 3) + (lane & 7));
                    uint32_t off = row*64 + (uint32_t)(ks*32) + (uint32_t)(((lane >> 3) & 1) << 4);
                    off ^= (off >> 3) & 0x30u;
                    uint32_t r4[4];
                    ldm4(r4, stg + 3*TILE_A + wj*TILE_W + off);
                    bfr[wj][nt2*2][0]=r4[0];   bfr[wj][nt2*2][1]=r4[1];
                    bfr[wj][nt2*2+1][0]=r4[2]; bfr[wj][nt2*2+1][1]=r4[3];
                }
            // 6 pair-groups: a1w1,a1w2,a1w3,a2w1,a2w2,a3w1
            const int PA[6] = {0,0,0,1,1,2};
            const int PW[6] = {0,1,2,0,1,0};
#pragma unroll
            for (int p = 0; p < 6; p++)
#pragma unroll
                for (int mt = 0; mt < 2; mt++)
#pragma unroll
                    for (int nt = 0; nt < 4; nt++)
                        mma16816(acc[mt][nt], afr[PA[p]][mt], bfr[PW[p]][nt]);
        }
        __syncthreads();
    }

    // ---- epilogue ----
    float* Cs = (float*)smem;
    {
        const int r0 = wm*32 + (lane >> 2);
        const int c0 = wn*32 + 2*(lane & 3);
#pragma unroll
        for (int mt = 0; mt < 2; mt++)
#pragma unroll
            for (int nt = 0; nt < 4; nt++){
                int row = r0 + mt*16, col = c0 + nt*8;
                Cs[row*129 + col]       = acc[mt][nt][0];
                Cs[row*129 + col + 1]   = acc[mt][nt][1];
                Cs[(row+8)*129 + col]   = acc[mt][nt][2];
                Cs[(row+8)*129 + col+1] = acc[mt][nt][3];
            }
    }
    __syncthreads();

    for (int idx = tid; idx < 64*128; idx += 256){
        int row = idx >> 7, c = idx & 127;
        int r = rb + row;
        if (r < R){
            float v = Cs[row*129 + c] + bias[ob + c];
            size_t g = (size_t)r*O + ob + c;
            if (RES) v += res[g];
            if (SPLITOUT){
                uint32_t t1,t2,t3;
                split3(v, t1,t2,t3);
                g_B1[g] = asbf(t1); g_B2[g] = asbf(t2); g_B3[g] = asbf(t3);
            } else {
                C[g] = v;
            }
        }
    }
}

// ---------------- attention: cp.async double-buffered K/V ------------------
// block per (qchunk, head, batch); 28 q rows; 4 tiles of 49 keys.
// Output written directly as 3-term bf16 split into g_A1/2/3.
#define ASM_Q   0
#define ASM_K0  1904
#define ASM_K1  5236
#define ASM_V0  8568
#define ASM_V1  11900
#define ASM_S   15232
#define ASM_FLOATS 16688   /* x4 = 66752 bytes */

__global__ void __launch_bounds__(256) attn_kernel()
{
    extern __shared__ __align__(16) float asmem[];
    const int qc = blockIdx.x, h = blockIdx.y, b = blockIdx.z;
    const int r0 = qc*28;
    const int tid = threadIdx.x, lane = tid & 31, w = tid >> 5;

    float* Qs = asmem + ASM_Q;
    float* S  = asmem + ASM_S;
    const uint32_t kbu[2] = {smem_u32(asmem + ASM_K0), smem_u32(asmem + ASM_K1)};
    const uint32_t vbu[2] = {smem_u32(asmem + ASM_V0), smem_u32(asmem + ASM_V1)};

    auto issue = [&](int t){
        const int buf = t & 1;
        for (int idx = tid; idx < 784; idx += 256){
            int j = idx >> 4, seg = idx & 15;
            size_t gb = (size_t)(b*NN + t*49 + j)*1536 + h*64 + seg*4;
            cp16(kbu[buf] + j*272 + seg*16, g_qkv + gb + 512);
            cp16(vbu[buf] + j*272 + seg*16, g_qkv + gb + 1024);
        }
        asm volatile("cp.async.commit_group;" ::: "memory");
    };

    issue(0);
    for (int idx=tid; idx<28*64; idx+=256){
        int row = idx>>6, kx = idx&63;
        Qs[row*68+kx] = g_qkv[(size_t)(b*NN + r0+row)*1536 + h*64 + kx];
    }

    const int nrows = (w<4)?4:3;
    float mrun[4], lrun[4], o0[4], o1[4];
#pragma unroll
    for (int rr=0; rr<4; rr++){ mrun[rr]=-1e30f; lrun[rr]=0.f; o0[rr]=0.f; o1[rr]=0.f; }

    const int srow = tid >> 3, jg = tid & 7;

    for (int t=0;t<4;t++){
        __syncthreads();                       // prev compute done / Q stores done
        if (t<3){
            issue(t+1);
            asm volatile("cp.async.wait_group 1;" ::: "memory");
        } else {
            asm volatile("cp.async.wait_group 0;" ::: "memory");
        }
        __syncthreads();                       // tile t visible

        const int buf = t & 1;
        const float* Ks = asmem + (buf ? ASM_K1 : ASM_K0);
        const float* Vs = asmem + (buf ? ASM_V1 : ASM_V0);

        // scores: thread -> (srow, j = jg + 8*jj)
        if (srow < 28){
            float acc[7];
#pragma unroll
            for (int jj=0;jj<7;jj++) acc[jj]=0.f;
            const float4* q4 = (const float4*)&Qs[srow*68];
#pragma unroll
            for (int kx=0; kx<16; kx++){
                float4 qa = q4[kx];
#pragma unroll
                for (int jj=0;jj<7;jj++){
                    int j = jg + 8*jj;
                    if (j < 49){
                        float4 ka = *(const float4*)&Ks[j*68 + kx*4];
                        acc[jj] += qa.x*ka.x + qa.y*ka.y + qa.z*ka.z + qa.w*ka.w;
                    }
                }
            }
#pragma unroll
            for (int jj=0;jj<7;jj++){
                int j = jg + 8*jj;
                if (j < 49) S[srow*52+j] = acc[jj]*0.125f;
            }
        }
        __syncthreads();

        // per-row softmax update
#pragma unroll
        for (int rr=0; rr<4; rr++){
            if (rr >= nrows) break;
            int row = w + 8*rr;
            float s0 = (lane<49) ? S[row*52+lane]    : -1e30f;
            float s1 = (lane<17) ? S[row*52+lane+32] : -1e30f;
            float tm = warp_max(fmaxf(s0,s1));
            float mnew = fmaxf(mrun[rr], tm);
            float alpha = __expf(mrun[rr]-mnew);
            float p0 = (lane<49) ? __expf(s0-mnew) : 0.f;
            float p1 = (lane<17) ? __expf(s1-mnew) : 0.f;
            float psum = warp_sum(p0+p1);
            lrun[rr] = lrun[rr]*alpha + psum;
            mrun[rr] = mnew;
            if (lane<49) S[row*52+lane]    = p0;
            if (lane<17) S[row*52+lane+32] = p1;
            o0[rr]*=alpha; o1[rr]*=alpha;
        }
        __syncwarp();
        // AV: hoisted V loads
        for (int j=0;j<49;j++){
            float v0 = Vs[j*68+lane];
            float v1 = Vs[j*68+lane+32];
#pragma unroll
            for (int rr=0; rr<4; rr++){
                if (rr >= nrows) break;
                float pj = S[(w + 8*rr)*52 + j];
                o0[rr] += pj * v0;
                o1[rr] += pj * v1;
            }
        }
    }
    // write 3-term bf16 split of attention output directly
    for (int rr=0; rr<nrows; rr++){
        int row = w + 8*rr;
        float inv = 1.f/lrun[rr];
        size_t base = (size_t)(b*NN + r0+row)*512 + h*64;
        uint32_t t1,t2,t3;
        split3(o0[rr]*inv, t1,t2,t3);
        g_A1[base+lane] = asbf(t1); g_A2[base+lane] = asbf(t2); g_A3[base+lane] = asbf(t3);
        split3(o1[rr]*inv, t1,t2,t3);
        g_A1[base+lane+32] = asbf(t1); g_A2[base+lane+32] = asbf(t2); g_A3[base+lane+32] = asbf(t3);
    }
}

// ---------------- fused LN + GELU + w2 + decompose --------------------------
__global__ void __launch_bounds__(256) ln_decomp(
    const float* __restrict__ hin, const float* __restrict__ lng,
    const float* __restrict__ lnb, const float* __restrict__ w2,
    const float* __restrict__ b2,
    const float* __restrict__ F, const float* __restrict__ tpl,
    const int* __restrict__ kptr, float* __restrict__ out)
{
    const int r = blockIdx.x, tid = threadIdx.x, lane = tid&31, w = tid>>5;
    __shared__ float fs[512];
    __shared__ float gs[512];
    __shared__ float red[16];
    __shared__ int hist[8][256];
    __shared__ unsigned int thr_s[MM];
    __shared__ float scale_s[MM];
    __shared__ unsigned int eqmask_s[MM][16];

    float x0 = hin[(size_t)r*512 + tid];
    float x1 = hin[(size_t)r*512 + tid + 256];
    fs[tid]     = F[(size_t)r*512 + tid];
    fs[tid+256] = F[(size_t)r*512 + tid + 256];

    float s  = warp_sum(x0 + x1);
    float sq = warp_sum(x0*x0 + x1*x1);
    if (lane==0){ red[w]=s; red[w+8]=sq; }
    __syncthreads();
    if (tid==0){
        float S=0,Q=0;
#pragma unroll
        for (int i=0;i<8;i++){ S+=red[i]; Q+=red[i+8]; }
        red[0]=S; red[1]=Q;
    }
    __syncthreads();
    float mean = red[0]*(1.f/512.f);
    float var  = red[1]*(1.f/512.f) - mean*mean;
    float rstd = rsqrtf(var + 1e-5f);
    {
        float y0 = (x0-mean)*rstd*lng[tid]     + lnb[tid];
        float y1 = (x1-mean)*rstd*lng[tid+256] + lnb[tid+256];
        gs[tid]     = 0.5f*y0*(1.f+erff(y0*0.70710678118654752f));
        gs[tid+256] = 0.5f*y1*(1.f+erff(y1*0.70710678118654752f));
    }
    __syncthreads();

    const int kval = *kptr;   // 51
    const int nm = (w<4) ? 3 : 2;
    float qpv[3];
    // qp for this warp's m values (all lanes get the sum via xor-reduction)
    for (int i=0; i<nm; i++){
        int m = w + 8*i;
        float acc = 0.f;
#pragma unroll
        for (int j=0;j<16;j++){
            int d = lane + 32*j;
            acc += gs[d]*w2[m*512+d];
        }
        qpv[i] = warp_sum(acc) + b2[m];
    }

    for (int i=0; i<nm; i++){
        int m = w + 8*i;
        float p[16]; unsigned int u[16];
#pragma unroll
        for (int j=0;j<16;j++){
            int d = lane + 32*j;
            p[j] = fs[d]*tpl[m*512+d];
            u[j] = __float_as_uint(fabsf(p[j]));
        }
        unsigned int pref=0u, pmask=0u; int kk = kval;
        const int shifts[4]  = {23,15,7,0};
        const unsigned int dmasks[4] = {0xFFu,0xFFu,0xFFu,0x7Fu};
#pragma unroll
        for (int ps=0; ps<4; ps++){
            const int sh = shifts[ps]; const unsigned int dm = dmasks[ps];
            for (int bI=lane; bI<256; bI+=32) hist[w][bI]=0;
            __syncwarp();
#pragma unroll
            for (int j=0;j<16;j++){
                if ((u[j] & pmask) == pref)
                    atomicAdd(&hist[w][(u[j]>>sh)&dm], 1);
            }
            __syncwarp();
            int base = 255 - 8*lane;
            int s8 = 0;
#pragma unroll
            for (int j=0;j<8;j++) s8 += hist[w][base-j];
            int incl = s8;
#pragma unroll
            for (int off=1; off<32; off<<=1){
                int v = __shfl_up_sync(0xffffffffu, incl, off);
                if (lane>=off) incl += v;
            }
            int excl = incl - s8;
            int dig = -1, kk2 = 0;
            if (excl < kk && incl >= kk){
                int run = excl;
#pragma unroll
                for (int j=0;j<8;j++){
                    int hc = hist[w][base-j];
                    if (dig<0 && run+hc >= kk){ dig = base-j; kk2 = kk-run; }
                    run += hc;
                }
            }
            unsigned int bal = __ballot_sync(0xffffffffu, dig>=0);
            int src = __ffs(bal)-1;
            dig = __shfl_sync(0xffffffffu, dig, src);
            kk  = __shfl_sync(0xffffffffu, kk2, src);
            pref  |= ((unsigned int)dig) << sh;
            pmask |= dm << sh;
            __syncwarp();
        }
        const unsigned int thr = pref;
        const int needeq = kk;

        if (lane<16) eqmask_s[m][lane]=0u;
        __syncwarp();
        float ss = 0.f; int eqbase = 0;
#pragma unroll
        for (int j=0;j<16;j++){
            bool eq = (u[j]==thr);
            unsigned int eb = __ballot_sync(0xffffffffu, eq);
            bool esel = eq && (eqbase + __popc(eb & ((1u<<lane)-1u)) < needeq);
            eqbase += __popc(eb);
            unsigned int sb2 = __ballot_sync(0xffffffffu, esel);
            if (lane==0) eqmask_s[m][j] = sb2;
            if (u[j] > thr || esel) ss += p[j]*p[j];
        }
        ss = warp_sum(ss);
        if (lane==0){
            float q = qpv[i];
            float nrm = fabsf(q)*sqrtf(ss);
            scale_s[m] = q / fmaxf(nrm, 1e-6f);
            thr_s[m]   = thr;
        }
    }
    __syncthreads();

    const size_t obase = (size_t)r * (512*MM);
    for (int lin=tid; lin<512*MM; lin+=256){
        int d = lin / MM, m = lin - d*MM;
        float pv = fs[d]*tpl[m*512+d];
        unsigned int uu = __float_as_uint(fabsf(pv));
        unsigned int thr = thr_s[m];
        bool sel = (uu > thr) ||
                   (uu == thr && ((eqmask_s[m][d>>5] >> (d&31)) & 1u));
        out[obase + lin] = sel ? pv*scale_s[m] : 0.f;
    }
}

// ---------------- launch ----------------
extern "C" void kernel_launch(void* const* d_in, const int* in_sizes, int n_in,
                              void* d_out, int out_size)
{
    (void)in_sizes; (void)n_in; (void)out_size;
    const float* F     = (const float*)d_in[0];
    const float* in_w  = (const float*)d_in[1];
    const float* in_b  = (const float*)d_in[2];
    const float* out_w = (const float*)d_in[3];
    const float* out_b = (const float*)d_in[4];
    const float* w1    = (const float*)d_in[5];
    const float* b1    = (const float*)d_in[6];
    const float* ln_g  = (const float*)d_in[7];
    const float* ln_b  = (const float*)d_in[8];
    const float* w2    = (const float*)d_in[9];
    const float* b2    = (const float*)d_in[10];
    const float* tpl   = (const float*)d_in[11];
    const int*   kptr  = (const int*)d_in[12];
    float* out = (float*)d_out;

    void *p_qkv, *p_h;
    void *pA1, *pA2, *pA3, *pB1, *pB2, *pB3, *pW1, *pW2, *pW3;
    cudaGetSymbolAddress(&p_qkv, g_qkv);
    cudaGetSymbolAddress(&p_h,   g_h);
    cudaGetSymbolAddress(&pA1, g_A1); cudaGetSymbolAddress(&pA2, g_A2);
    cudaGetSymbolAddress(&pA3, g_A3);
    cudaGetSymbolAddress(&pB1, g_B1); cudaGetSymbolAddress(&pB2, g_B2);
    cudaGetSymbolAddress(&pB3, g_B3);
    cudaGetSymbolAddress(&pW1, g_W1); cudaGetSymbolAddress(&pW2, g_W2);
    cudaGetSymbolAddress(&pW3, g_W3);
    float* qkv = (float*)p_qkv;
    float* hb  = (float*)p_h;
    __nv_bfloat16 *A1=(__nv_bfloat16*)pA1, *A2=(__nv_bfloat16*)pA2, *A3=(__nv_bfloat16*)pA3;
    __nv_bfloat16 *B1=(__nv_bfloat16*)pB1, *B2=(__nv_bfloat16*)pB2, *B3=(__nv_bfloat16*)pB3;
    __nv_bfloat16 *W1=(__nv_bfloat16*)pW1, *W2=(__nv_bfloat16*)pW2, *W3=(__nv_bfloat16*)pW3;

    cudaFuncSetAttribute((const void*)gemm_bf<false,false>,
                         cudaFuncAttributeMaxDynamicSharedMemorySize, GSM_SIZE);
    cudaFuncSetAttribute((const void*)gemm_bf<true,true>,
                         cudaFuncAttributeMaxDynamicSharedMemorySize, GSM_SIZE);
    cudaFuncSetAttribute((const void*)attn_kernel,
                         cudaFuncAttributeMaxDynamicSharedMemorySize, ASM_FLOATS*4);

    const int gy = (RTOT + 63) / 64;   // 49
    const int nA4 = RTOT*DD/4;

    // weight splits
    split_mat<<<(1536*DD/4 + 255)/256, 256>>>(in_w,  W1, W2, W3, 1536*DD/4);
    split_mat<<<(512*DD/4 + 255)/256, 256>>>(out_w, W1+1536*DD, W2+1536*DD, W3+1536*DD, 512*DD/4);
    split_mat<<<(512*DD/4 + 255)/256, 256>>>(w1,    W1+2048*DD, W2+2048*DD, W3+2048*DD, 512*DD/4);

    // 1) qkv = F @ in_w^T + in_b
    split_mat<<<(nA4 + 255)/256, 256>>>(F, A1, A2, A3, nA4);
    gemm_bf<false,false><<<dim3(12, gy), 256, GSM_SIZE>>>(A1, A2, A3, W1, W2, W3,
                                                          in_b, nullptr, qkv, RTOT, DD, 1536);
    // 2) attention -> writes att splits into g_A1/2/3
    attn_kernel<<<dim3(7, HH, BB), 256, ASM_FLOATS*4>>>();
    // 3) F_enh = att @ out_w^T + out_b + F  -> split directly into g_B1/2/3
    gemm_bf<true,true><<<dim3(4, gy), 256, GSM_SIZE>>>(A1, A2, A3,
        W1+1536*DD, W2+1536*DD, W3+1536*DD, out_b, F, hb, RTOT, DD, 512);
    // 4) h = F_enh @ w1^T + b1
    gemm_bf<false,false><<<dim3(4, gy), 256, GSM_SIZE>>>(B1, B2, B3,
        W1+2048*DD, W2+2048*DD, W3+2048*DD, b1, nullptr, hb, RTOT, DD, 512);
    // 5+6) fused LN + GELU + w2 + decompose
    ln_decomp<<<RTOT, 256>>>(hb, ln_g, ln_b, w2, b2, F, tpl, kptr, out);
}

// round 9
// speedup vs baseline: 1.5415x; 1.0202x over previous
#include <cuda_runtime.h>
#include <cuda_bf16.h>
#include <math.h>
#include <stdint.h>

#define BB 16
#define NN 196
#define DD 512
#define MM 20
#define HH 8
#define HD 64
#define RTOT (BB*NN)   /* 3136 */
#define WROWS 2560     /* in_w 1536 + out_w 512 + w1 512 */

// ---------------- scratch (device globals; no allocation) ----------------
__device__ float g_qkv[RTOT*3*DD];
__device__ float g_h[RTOT*DD];
__device__ __nv_bfloat16 g_A1[RTOT*DD], g_A2[RTOT*DD], g_A3[RTOT*DD];
__device__ __nv_bfloat16 g_B1[RTOT*DD], g_B2[RTOT*DD], g_B3[RTOT*DD];
__device__ __nv_bfloat16 g_W1[WROWS*DD], g_W2[WROWS*DD], g_W3[WROWS*DD];

// ---------------- warp helpers ----------------
__device__ __forceinline__ float warp_sum(float v){
#pragma unroll
    for (int off=16; off; off>>=1) v += __shfl_xor_sync(0xffffffffu, v, off);
    return v;
}
__device__ __forceinline__ float warp_max(float v){
#pragma unroll
    for (int off=16; off; off>>=1) v = fmaxf(v, __shfl_xor_sync(0xffffffffu, v, off));
    return v;
}

// ---------------- mma.sync / cp.async helpers ----------------
__device__ __forceinline__ uint32_t smem_u32(const void* p){
    uint32_t a;
    asm("{ .reg .u64 t; cvta.to.shared.u64 t, %1; cvt.u32.u64 %0, t; }" : "=r"(a) : "l"(p));
    return a;
}
__device__ __forceinline__ void ldm4(uint32_t* r, uint32_t addr){
    asm volatile("ldmatrix.sync.aligned.m8n8.x4.shared.b16 {%0,%1,%2,%3}, [%4];"
        : "=r"(r[0]),"=r"(r[1]),"=r"(r[2]),"=r"(r[3]) : "r"(addr));
}
__device__ __forceinline__ void mma16816(float* c, const uint32_t* a, const uint32_t* b){
    asm volatile("mma.sync.aligned.m16n8k16.row.col.f32.bf16.bf16.f32 "
        "{%0,%1,%2,%3}, {%4,%5,%6,%7}, {%8,%9}, {%0,%1,%2,%3};"
        : "+f"(c[0]),"+f"(c[1]),"+f"(c[2]),"+f"(c[3])
        : "r"(a[0]),"r"(a[1]),"r"(a[2]),"r"(a[3]), "r"(b[0]),"r"(b[1]));
}
__device__ __forceinline__ void cp16(uint32_t dst, const void* src){
    uint64_t g = __cvta_generic_to_global(src);
    asm volatile("cp.async.ca.shared.global [%0], [%1], 16;" :: "r"(dst), "l"(g) : "memory");
}

// 3-way bf16 cascade split: v = h1 + h2 + h3 + O(2^-27 |v|)
__device__ __forceinline__ void split3(float v, uint32_t& t1, uint32_t& t2, uint32_t& t3){
    __nv_bfloat16 h1 = __float2bfloat16_rn(v);
    float r1 = v - __bfloat162float(h1);
    __nv_bfloat16 h2 = __float2bfloat16_rn(r1);
    float r2 = r1 - __bfloat162float(h2);
    __nv_bfloat16 h3 = __float2bfloat16_rn(r2);
    t1 = (uint32_t)__bfloat16_as_ushort(h1);
    t2 = (uint32_t)__bfloat16_as_ushort(h2);
    t3 = (uint32_t)__bfloat16_as_ushort(h3);
}
__device__ __forceinline__ __nv_bfloat16 asbf(uint32_t t){
    return __ushort_as_bfloat16((unsigned short)t);
}

// ---------------- pre-split kernels -----------------------------------------
__global__ void __launch_bounds__(256) split_mat(
    const float* __restrict__ X,
    __nv_bfloat16* __restrict__ o1, __nv_bfloat16* __restrict__ o2,
    __nv_bfloat16* __restrict__ o3, int n4)
{
    int i = blockIdx.x*256 + threadIdx.x;
    if (i >= n4) return;
    float4 v = *(const float4*)&X[(size_t)i*4];
    uint32_t x1,x2,x3, y1,y2,y3, z1,z2,z3, u1,u2,u3;
    split3(v.x, x1,x2,x3); split3(v.y, y1,y2,y3);
    split3(v.z, z1,z2,z3); split3(v.w, u1,u2,u3);
    *(uint2*)&o1[(size_t)i*4] = make_uint2(x1|(y1<<16), z1|(u1<<16));
    *(uint2*)&o2[(size_t)i*4] = make_uint2(x2|(y2<<16), z2|(u2<<16));
    *(uint2*)&o3[(size_t)i*4] = make_uint2(x3|(y3<<16), z3|(u3<<16));
}

// all three weight matrices in one launch (segments of g_W*)
__global__ void __launch_bounds__(256) split_weights(
    const float* __restrict__ in_w, const float* __restrict__ out_w,
    const float* __restrict__ w1)
{
    int i = blockIdx.x*256 + threadIdx.x;     // float4 index, 2560*128 total
    if (i >= WROWS*128) return;
    int row = i >> 7;
    const float* src; int off;
    if (row < 1536){ src = in_w;  off = i; }
    else if (row < 2048){ src = out_w; off = i - 1536*128; }
    else { src = w1; off = i - 2048*128; }
    float4 v = ((const float4*)src)[off];
    uint32_t x1,x2,x3, y1,y2,y3, z1,z2,z3, u1,u2,u3;
    split3(v.x, x1,x2,x3); split3(v.y, y1,y2,y3);
    split3(v.z, z1,z2,z3); split3(v.w, u1,u2,u3);
    *(uint2*)&g_W1[(size_t)i*4] = make_uint2(x1|(y1<<16), z1|(u1<<16));
    *(uint2*)&g_W2[(size_t)i*4] = make_uint2(x2|(y2<<16), z2|(u2<<16));
    *(uint2*)&g_W3[(size_t)i*4] = make_uint2(x3|(y3<<16), z3|(u3<<16));
}

// ---------------- pure-bf16 tensor-core GEMM, 4-stage cp.async ring ---------
#define TILE_A   4096
#define TILE_W   8192
#define STAGE_B  (3*TILE_A + 3*TILE_W)   /* 36864 */
#define NSTAGE   4
#define GSM_SIZE (NSTAGE*STAGE_B)        /* 147456 */

template<bool RES, bool SPLITOUT>
__global__ void __launch_bounds__(256) gemm_bf(
    const __nv_bfloat16* __restrict__ A1, const __nv_bfloat16* __restrict__ A2,
    const __nv_bfloat16* __restrict__ A3,
    const __nv_bfloat16* __restrict__ W1, const __nv_bfloat16* __restrict__ W2,
    const __nv_bfloat16* __restrict__ W3,
    const float* __restrict__ bias, const float* __restrict__ res,
    float* __restrict__ C, int R, int K, int O)
{
    extern __shared__ __align__(128) char smem[];
    const uint32_t sb = smem_u32(smem);
    const int tid = threadIdx.x, lane = tid & 31, wid = tid >> 5;
    const int rb = blockIdx.y * 64, ob = blockIdx.x * 128;
    const int wm = wid & 1, wn = wid >> 1;

    float acc[2][4][4];
#pragma unroll
    for (int i=0;i<2;i++)
#pragma unroll
        for (int j=0;j<4;j++)
#pragma unroll
            for (int q=0;q<4;q++) acc[i][j][q]=0.f;

    const __nv_bfloat16* As[3] = {A1, A2, A3};
    const __nv_bfloat16* Ws[3] = {W1, W2, W3};

    const int ar = tid >> 2, aq = tid & 3;
    int gra = rb + ar; if (gra >= R) gra = R - 1;
    uint32_t aoffsw = (uint32_t)(ar*64 + aq*16); aoffsw ^= (aoffsw>>3) & 0x30u;

    auto issue_chunk = [&](int c){
        const uint32_t base = sb + (uint32_t)(c & (NSTAGE-1))*STAGE_B;
        const int k0 = c*32;
#pragma unroll
        for (int t = 0; t < 3; t++)
            cp16(base + t*TILE_A + aoffsw, As[t] + (size_t)gra*K + k0 + aq*8);
#pragma unroll
        for (int j = 0; j < 6; j++){
            int wi = j >> 1;
            int r  = (j & 1)*64 + (tid >> 2);
            int q  = tid & 3;
            uint32_t off = (uint32_t)(r*64 + q*16); off ^= (off>>3) & 0x30u;
            cp16(base + 3*TILE_A + wi*TILE_W + off, Ws[wi] + (size_t)(ob + r)*K + k0 + q*8);
        }
        asm volatile("cp.async.commit_group;" ::: "memory");
    };

    const int NTc = K / 32;
    issue_chunk(0);
    if (1 < NTc) issue_chunk(1);
    if (2 < NTc) issue_chunk(2);

    for (int c = 0; c < NTc; c++){
        const int inflight = NTc - 1 - c;
        if (inflight >= 2)      asm volatile("cp.async.wait_group 2;" ::: "memory");
        else if (inflight == 1) asm volatile("cp.async.wait_group 1;" ::: "memory");
        else                    asm volatile("cp.async.wait_group 0;" ::: "memory");
        __syncthreads();                      // chunk c visible; compute(c-1) done by all
        if (c+3 < NTc) issue_chunk(c+3);      // safe: overwrites buffer of chunk c-1

        const uint32_t stg = sb + (uint32_t)(c & (NSTAGE-1))*STAGE_B;
#pragma unroll
        for (int ks = 0; ks < 2; ks++){
            uint32_t afr[3][2][4];
#pragma unroll
            for (int ai = 0; ai < 3; ai++)
#pragma unroll
                for (int mt = 0; mt < 2; mt++){
                    uint32_t row = (uint32_t)(wm*32 + mt*16 + (lane & 15));
                    uint32_t off = row*64 + (uint32_t)(ks*32) + (uint32_t)((lane >> 4) << 4);
                    off ^= (off >> 3) & 0x30u;
                    ldm4(afr[ai][mt], stg + ai*TILE_A + off);
                }
            uint32_t bfr[3][4][2];
#pragma unroll
            for (int wj = 0; wj < 3; wj++)
#pragma unroll
                for (int nt2 = 0; nt2 < 2; nt2++){
                    uint32_t row = (uint32_t)(wn*32 + nt2*16 + ((lane >> 4) << 3) + (lane & 7));
                    uint32_t off = row*64 + (uint32_t)(ks*32) + (uint32_t)(((lane >> 3) & 1) << 4);
                    off ^= (off >> 3) & 0x30u;
                    uint32_t r4[4];
                    ldm4(r4, stg + 3*TILE_A + wj*TILE_W + off);
                    bfr[wj][nt2*2][0]=r4[0];   bfr[wj][nt2*2][1]=r4[1];
                    bfr[wj][nt2*2+1][0]=r4[2]; bfr[wj][nt2*2+1][1]=r4[3];
                }
            const int PA[6] = {0,0,0,1,1,2};
            const int PW[6] = {0,1,2,0,1,0};
#pragma unroll
            for (int p = 0; p < 6; p++)
#pragma unroll
                for (int mt = 0; mt < 2; mt++)
#pragma unroll
                    for (int nt = 0; nt < 4; nt++)
                        mma16816(acc[mt][nt], afr[PA[p]][mt], bfr[PW[p]][nt]);
        }
    }
    __syncthreads();                           // all compute done before smem reuse

    // ---- epilogue ----
    float* Cs = (float*)smem;
    {
        const int r0 = wm*32 + (lane >> 2);
        const int c0 = wn*32 + 2*(lane & 3);
#pragma unroll
        for (int mt = 0; mt < 2; mt++)
#pragma unroll
            for (int nt = 0; nt < 4; nt++){
                int row = r0 + mt*16, col = c0 + nt*8;
                Cs[row*129 + col]       = acc[mt][nt][0];
                Cs[row*129 + col + 1]   = acc[mt][nt][1];
                Cs[(row+8)*129 + col]   = acc[mt][nt][2];
                Cs[(row+8)*129 + col+1] = acc[mt][nt][3];
            }
    }
    __syncthreads();

    for (int idx = tid; idx < 64*128; idx += 256){
        int row = idx >> 7, c = idx & 127;
        int r = rb + row;
        if (r < R){
            float v = Cs[row*129 + c] + bias[ob + c];
            size_t g = (size_t)r*O + ob + c;
            if (RES) v += res[g];
            if (SPLITOUT){
                uint32_t t1,t2,t3;
                split3(v, t1,t2,t3);
                g_B1[g] = asbf(t1); g_B2[g] = asbf(t2); g_B3[g] = asbf(t3);
            } else {
                C[g] = v;
            }
        }
    }
}

// ---------------- attention: cp.async double-buffered K/V ------------------
#define ASM_Q   0
#define ASM_K0  1904
#define ASM_K1  5236
#define ASM_V0  8568
#define ASM_V1  11900
#define ASM_S   15232
#define ASM_FLOATS 16688   /* x4 = 66752 bytes */

__global__ void __launch_bounds__(256) attn_kernel()
{
    extern __shared__ __align__(16) float asmem[];
    const int qc = blockIdx.x, h = blockIdx.y, b = blockIdx.z;
    const int r0 = qc*28;
    const int tid = threadIdx.x, lane = tid & 31, w = tid >> 5;

    float* Qs = asmem + ASM_Q;
    float* S  = asmem + ASM_S;
    const uint32_t kbu[2] = {smem_u32(asmem + ASM_K0), smem_u32(asmem + ASM_K1)};
    const uint32_t vbu[2] = {smem_u32(asmem + ASM_V0), smem_u32(asmem + ASM_V1)};

    auto issue = [&](int t){
        const int buf = t & 1;
        for (int idx = tid; idx < 784; idx += 256){
            int j = idx >> 4, seg = idx & 15;
            size_t gb = (size_t)(b*NN + t*49 + j)*1536 + h*64 + seg*4;
            cp16(kbu[buf] + j*272 + seg*16, g_qkv + gb + 512);
            cp16(vbu[buf] + j*272 + seg*16, g_qkv + gb + 1024);
        }
        asm volatile("cp.async.commit_group;" ::: "memory");
    };

    issue(0);
    for (int idx=tid; idx<28*64; idx+=256){
        int row = idx>>6, kx = idx&63;
        Qs[row*68+kx] = g_qkv[(size_t)(b*NN + r0+row)*1536 + h*64 + kx];
    }

    const int nrows = (w<4)?4:3;
    float mrun[4], lrun[4], o0[4], o1[4];
#pragma unroll
    for (int rr=0; rr<4; rr++){ mrun[rr]=-1e30f; lrun[rr]=0.f; o0[rr]=0.f; o1[rr]=0.f; }

    const int srow = tid >> 3, jg = tid & 7;

    for (int t=0;t<4;t++){
        __syncthreads();
        if (t<3){
            issue(t+1);
            asm volatile("cp.async.wait_group 1;" ::: "memory");
        } else {
            asm volatile("cp.async.wait_group 0;" ::: "memory");
        }
        __syncthreads();

        const int buf = t & 1;
        const float* Ks = asmem + (buf ? ASM_K1 : ASM_K0);
        const float* Vs = asmem + (buf ? ASM_V1 : ASM_V0);

        if (srow < 28){
            float acc[7];
#pragma unroll
            for (int jj=0;jj<7;jj++) acc[jj]=0.f;
            const float4* q4 = (const float4*)&Qs[srow*68];
#pragma unroll
            for (int kx=0; kx<16; kx++){
                float4 qa = q4[kx];
#pragma unroll
                for (int jj=0;jj<7;jj++){
                    int j = jg + 8*jj;
                    if (j < 49){
                        float4 ka = *(const float4*)&Ks[j*68 + kx*4];
                        acc[jj] += qa.x*ka.x + qa.y*ka.y + qa.z*ka.z + qa.w*ka.w;
                    }
                }
            }
#pragma unroll
            for (int jj=0;jj<7;jj++){
                int j = jg + 8*jj;
                if (j < 49) S[srow*52+j] = acc[jj]*0.125f;
            }
        }
        __syncthreads();

#pragma unroll
        for (int rr=0; rr<4; rr++){
            if (rr >= nrows) break;
            int row = w + 8*rr;
            float s0 = (lane<49) ? S[row*52+lane]    : -1e30f;
            float s1 = (lane<17) ? S[row*52+lane+32] : -1e30f;
            float tm = warp_max(fmaxf(s0,s1));
            float mnew = fmaxf(mrun[rr], tm);
            float alpha = __expf(mrun[rr]-mnew);
            float p0 = (lane<49) ? __expf(s0-mnew) : 0.f;
            float p1 = (lane<17) ? __expf(s1-mnew) : 0.f;
            float psum = warp_sum(p0+p1);
            lrun[rr] = lrun[rr]*alpha + psum;
            mrun[rr] = mnew;
            if (lane<49) S[row*52+lane]    = p0;
            if (lane<17) S[row*52+lane+32] = p1;
            o0[rr]*=alpha; o1[rr]*=alpha;
        }
        __syncwarp();
        for (int j=0;j<49;j++){
            float v0 = Vs[j*68+lane];
            float v1 = Vs[j*68+lane+32];
#pragma unroll
            for (int rr=0; rr<4; rr++){
                if (rr >= nrows) break;
                float pj = S[(w + 8*rr)*52 + j];
                o0[rr] += pj * v0;
                o1[rr] += pj * v1;
            }
        }
    }
    for (int rr=0; rr<nrows; rr++){
        int row = w + 8*rr;
        float inv = 1.f/lrun[rr];
        size_t base = (size_t)(b*NN + r0+row)*512 + h*64;
        uint32_t t1,t2,t3;
        split3(o0[rr]*inv, t1,t2,t3);
        g_A1[base+lane] = asbf(t1); g_A2[base+lane] = asbf(t2); g_A3[base+lane] = asbf(t3);
        split3(o1[rr]*inv, t1,t2,t3);
        g_A1[base+lane+32] = asbf(t1); g_A2[base+lane+32] = asbf(t2); g_A3[base+lane+32] = asbf(t3);
    }
}

// ---------------- fused LN + GELU + w2 + decompose --------------------------
__global__ void __launch_bounds__(256) ln_decomp(
    const float* __restrict__ hin, const float* __restrict__ lng,
    const float* __restrict__ lnb, const float* __restrict__ w2,
    const float* __restrict__ b2,
    const float* __restrict__ F, const float* __restrict__ tpl,
    const int* __restrict__ kptr, float* __restrict__ out)
{
    const int r = blockIdx.x, tid = threadIdx.x, lane = tid&31, w = tid>>5;
    __shared__ float fs[512];
    __shared__ float gs[512];
    __shared__ float red[16];
    __shared__ int hist[8][256];
    __shared__ unsigned int thr_s[MM];
    __shared__ float scale_s[MM];
    __shared__ unsigned int eqmask_s[MM][16];

    float x0 = hin[(size_t)r*512 + tid];
    float x1 = hin[(size_t)r*512 + tid + 256];
    fs[tid]     = F[(size_t)r*512 + tid];
    fs[tid+256] = F[(size_t)r*512 + tid + 256];

    float s  = warp_sum(x0 + x1);
    float sq = warp_sum(x0*x0 + x1*x1);
    if (lane==0){ red[w]=s; red[w+8]=sq; }
    __syncthreads();
    if (tid==0){
        float S=0,Q=0;
#pragma unroll
        for (int i=0;i<8;i++){ S+=red[i]; Q+=red[i+8]; }
        red[0]=S; red[1]=Q;
    }
    __syncthreads();
    float mean = red[0]*(1.f/512.f);
    float var  = red[1]*(1.f/512.f) - mean*mean;
    float rstd = rsqrtf(var + 1e-5f);
    {
        float y0 = (x0-mean)*rstd*lng[tid]     + lnb[tid];
        float y1 = (x1-mean)*rstd*lng[tid+256] + lnb[tid+256];
        gs[tid]     = 0.5f*y0*(1.f+erff(y0*0.70710678118654752f));
        gs[tid+256] = 0.5f*y1*(1.f+erff(y1*0.70710678118654752f));
    }
    __syncthreads();

    const int kval = *kptr;   // 51
    const int nm = (w<4) ? 3 : 2;
    float qpv[3];
    for (int i=0; i<nm; i++){
        int m = w + 8*i;
        float acc = 0.f;
#pragma unroll
        for (int j=0;j<16;j++){
            int d = lane + 32*j;
            acc += gs[d]*w2[m*512+d];
        }
        qpv[i] = warp_sum(acc) + b2[m];
    }

    for (int i=0; i<nm; i++){
        int m = w + 8*i;
        float p[16]; unsigned int u[16];
#pragma unroll
        for (int j=0;j<16;j++){
            int d = lane + 32*j;
            p[j] = fs[d]*tpl[m*512+d];
            u[j] = __float_as_uint(fabsf(p[j]));
        }
        unsigned int pref=0u, pmask=0u; int kk = kval;
        const int shifts[4]  = {23,15,7,0};
        const unsigned int dmasks[4] = {0xFFu,0xFFu,0xFFu,0x7Fu};
#pragma unroll
        for (int ps=0; ps<4; ps++){
            const int sh = shifts[ps]; const unsigned int dm = dmasks[ps];
            for (int bI=lane; bI<256; bI+=32) hist[w][bI]=0;
            __syncwarp();
#pragma unroll
            for (int j=0;j<16;j++){
                if ((u[j] & pmask) == pref)
                    atomicAdd(&hist[w][(u[j]>>sh)&dm], 1);
            }
            __syncwarp();
            int base = 255 - 8*lane;
            int s8 = 0;
#pragma unroll
            for (int j=0;j<8;j++) s8 += hist[w][base-j];
            int incl = s8;
#pragma unroll
            for (int off=1; off<32; off<<=1){
                int v = __shfl_up_sync(0xffffffffu, incl, off);
                if (lane>=off) incl += v;
            }
            int excl = incl - s8;
            int dig = -1, kk2 = 0;
            if (excl < kk && incl >= kk){
                int run = excl;
#pragma unroll
                for (int j=0;j<8;j++){
                    int hc = hist[w][base-j];
                    if (dig<0 && run+hc >= kk){ dig = base-j; kk2 = kk-run; }
                    run += hc;
                }
            }
            unsigned int bal = __ballot_sync(0xffffffffu, dig>=0);
            int src = __ffs(bal)-1;
            dig = __shfl_sync(0xffffffffu, dig, src);
            kk  = __shfl_sync(0xffffffffu, kk2, src);
            pref  |= ((unsigned int)dig) << sh;
            pmask |= dm << sh;
            __syncwarp();
        }
        const unsigned int thr = pref;
        const int needeq = kk;

        if (lane<16) eqmask_s[m][lane]=0u;
        __syncwarp();
        float ss = 0.f; int eqbase = 0;
#pragma unroll
        for (int j=0;j<16;j++){
            bool eq = (u[j]==thr);
            unsigned int eb = __ballot_sync(0xffffffffu, eq);
            bool esel = eq && (eqbase + __popc(eb & ((1u<<lane)-1u)) < needeq);
            eqbase += __popc(eb);
            unsigned int sb2 = __ballot_sync(0xffffffffu, esel);
            if (lane==0) eqmask_s[m][j] = sb2;
            if (u[j] > thr || esel) ss += p[j]*p[j];
        }
        ss = warp_sum(ss);
        if (lane==0){
            float q = qpv[i];
            float nrm = fabsf(q)*sqrtf(ss);
            scale_s[m] = q / fmaxf(nrm, 1e-6f);
            thr_s[m]   = thr;
        }
    }
    __syncthreads();

    // output: float4 stores, fully coalesced
    const size_t obase = (size_t)r * (512*MM);
    for (int base = tid*4; base < 512*MM; base += 1024){
        float4 vv;
        float* pv4 = (float*)&vv;
#pragma unroll
        for (int e=0;e<4;e++){
            int lin = base + e;
            int d = lin / MM, m = lin - d*MM;
            float pv = fs[d]*tpl[m*512+d];
            unsigned int uu = __float_as_uint(fabsf(pv));
            unsigned int thr = thr_s[m];
            bool sel = (uu > thr) ||
                       (uu == thr && ((eqmask_s[m][d>>5] >> (d&31)) & 1u));
            pv4[e] = sel ? pv*scale_s[m] : 0.f;
        }
        *(float4*)&out[obase + base] = vv;
    }
}

// ---------------- launch ----------------
extern "C" void kernel_launch(void* const* d_in, const int* in_sizes, int n_in,
                              void* d_out, int out_size)
{
    (void)in_sizes; (void)n_in; (void)out_size;
    const float* F     = (const float*)d_in[0];
    const float* in_w  = (const float*)d_in[1];
    const float* in_b  = (const float*)d_in[2];
    const float* out_w = (const float*)d_in[3];
    const float* out_b = (const float*)d_in[4];
    const float* w1    = (const float*)d_in[5];
    const float* b1    = (const float*)d_in[6];
    const float* ln_g  = (const float*)d_in[7];
    const float* ln_b  = (const float*)d_in[8];
    const float* w2    = (const float*)d_in[9];
    const float* b2    = (const float*)d_in[10];
    const float* tpl   = (const float*)d_in[11];
    const int*   kptr  = (const int*)d_in[12];
    float* out = (float*)d_out;

    void *p_qkv, *p_h;
    void *pA1, *pA2, *pA3, *pB1, *pB2, *pB3, *pW1, *pW2, *pW3;
    cudaGetSymbolAddress(&p_qkv, g_qkv);
    cudaGetSymbolAddress(&p_h,   g_h);
    cudaGetSymbolAddress(&pA1, g_A1); cudaGetSymbolAddress(&pA2, g_A2);
    cudaGetSymbolAddress(&pA3, g_A3);
    cudaGetSymbolAddress(&pB1, g_B1); cudaGetSymbolAddress(&pB2, g_B2);
    cudaGetSymbolAddress(&pB3, g_B3);
    cudaGetSymbolAddress(&pW1, g_W1); cudaGetSymbolAddress(&pW2, g_W2);
    cudaGetSymbolAddress(&pW3, g_W3);
    float* qkv = (float*)p_qkv;
    float* hb  = (float*)p_h;
    __nv_bfloat16 *A1=(__nv_bfloat16*)pA1, *A2=(__nv_bfloat16*)pA2, *A3=(__nv_bfloat16*)pA3;
    __nv_bfloat16 *B1=(__nv_bfloat16*)pB1, *B2=(__nv_bfloat16*)pB2, *B3=(__nv_bfloat16*)pB3;
    __nv_bfloat16 *W1=(__nv_bfloat16*)pW1, *W2=(__nv_bfloat16*)pW2, *W3=(__nv_bfloat16*)pW3;

    cudaFuncSetAttribute((const void*)gemm_bf<false,false>,
                         cudaFuncAttributeMaxDynamicSharedMemorySize, GSM_SIZE);
    cudaFuncSetAttribute((const void*)gemm_bf<true,true>,
                         cudaFuncAttributeMaxDynamicSharedMemorySize, GSM_SIZE);
    cudaFuncSetAttribute((const void*)attn_kernel,
                         cudaFuncAttributeMaxDynamicSharedMemorySize, ASM_FLOATS*4);

    const int gy = (RTOT + 63) / 64;   // 49
    const int nA4 = RTOT*DD/4;

    // all weight splits in one launch
    split_weights<<<(WROWS*128 + 255)/256, 256>>>(in_w, out_w, w1);

    // 1) qkv = F @ in_w^T + in_b
    split_mat<<<(nA4 + 255)/256, 256>>>(F, A1, A2, A3, nA4);
    gemm_bf<false,false><<<dim3(12, gy), 256, GSM_SIZE>>>(A1, A2, A3, W1, W2, W3,
                                                          in_b, nullptr, qkv, RTOT, DD, 1536);
    // 2) attention -> writes att splits into g_A1/2/3
    attn_kernel<<<dim3(7, HH, BB), 256, ASM_FLOATS*4>>>();
    // 3) F_enh = att @ out_w^T + out_b + F  -> split directly into g_B1/2/3
    gemm_bf<true,true><<<dim3(4, gy), 256, GSM_SIZE>>>(A1, A2, A3,
        W1+1536*DD, W2+1536*DD, W3+1536*DD, out_b, F, hb, RTOT, DD, 512);
    // 4) h = F_enh @ w1^T + b1
    gemm_bf<false,false><<<dim3(4, gy), 256, GSM_SIZE>>>(B1, B2, B3,
        W1+2048*DD, W2+2048*DD, W3+2048*DD, b1, nullptr, hb, RTOT, DD, 512);
    // 5+6) fused LN + GELU + w2 + decompose
    ln_decomp<<<RTOT, 256>>>(hb, ln_g, ln_b, w2, b2, F, tpl, kptr, out);
}

// round 10
// speedup vs baseline: 1.5720x; 1.0198x over previous
#include <cuda_runtime.h>
#include <cuda_bf16.h>
#include <math.h>
#include <stdint.h>

#define BB 16
#define NN 196
#define DD 512
#define MM 20
#define HH 8
#define HD 64
#define RTOT (BB*NN)   /* 3136 */
#define WROWS 2560     /* in_w 1536 + out_w 512 + w1 512 */

// ---------------- scratch (device globals; no allocation) ----------------
__device__ float g_qkv[RTOT*3*DD];
__device__ float g_h[RTOT*DD];
__device__ __nv_bfloat16 g_A1[RTOT*DD], g_A2[RTOT*DD], g_A3[RTOT*DD];
__device__ __nv_bfloat16 g_B1[RTOT*DD], g_B2[RTOT*DD], g_B3[RTOT*DD];
__device__ __nv_bfloat16 g_W1[WROWS*DD], g_W2[WROWS*DD], g_W3[WROWS*DD];

// ---------------- warp helpers ----------------
__device__ __forceinline__ float warp_sum(float v){
#pragma unroll
    for (int off=16; off; off>>=1) v += __shfl_xor_sync(0xffffffffu, v, off);
    return v;
}
__device__ __forceinline__ float warp_max(float v){
#pragma unroll
    for (int off=16; off; off>>=1) v = fmaxf(v, __shfl_xor_sync(0xffffffffu, v, off));
    return v;
}

// ---------------- mma.sync / cp.async helpers ----------------
__device__ __forceinline__ uint32_t smem_u32(const void* p){
    uint32_t a;
    asm("{ .reg .u64 t; cvta.to.shared.u64 t, %1; cvt.u32.u64 %0, t; }" : "=r"(a) : "l"(p));
    return a;
}
__device__ __forceinline__ void ldm4(uint32_t* r, uint32_t addr){
    asm volatile("ldmatrix.sync.aligned.m8n8.x4.shared.b16 {%0,%1,%2,%3}, [%4];"
        : "=r"(r[0]),"=r"(r[1]),"=r"(r[2]),"=r"(r[3]) : "r"(addr));
}
__device__ __forceinline__ void mma16816(float* c, const uint32_t* a, const uint32_t* b){
    asm volatile("mma.sync.aligned.m16n8k16.row.col.f32.bf16.bf16.f32 "
        "{%0,%1,%2,%3}, {%4,%5,%6,%7}, {%8,%9}, {%0,%1,%2,%3};"
        : "+f"(c[0]),"+f"(c[1]),"+f"(c[2]),"+f"(c[3])
        : "r"(a[0]),"r"(a[1]),"r"(a[2]),"r"(a[3]), "r"(b[0]),"r"(b[1]));
}
__device__ __forceinline__ void cp16(uint32_t dst, const void* src){
    uint64_t g = __cvta_generic_to_global(src);
    asm volatile("cp.async.ca.shared.global [%0], [%1], 16;" :: "r"(dst), "l"(g) : "memory");
}

// 3-way bf16 cascade split: v = h1 + h2 + h3 + O(2^-27 |v|)
__device__ __forceinline__ void split3(float v, uint32_t& t1, uint32_t& t2, uint32_t& t3){
    __nv_bfloat16 h1 = __float2bfloat16_rn(v);
    float r1 = v - __bfloat162float(h1);
    __nv_bfloat16 h2 = __float2bfloat16_rn(r1);
    float r2 = r1 - __bfloat162float(h2);
    __nv_bfloat16 h3 = __float2bfloat16_rn(r2);
    t1 = (uint32_t)__bfloat16_as_ushort(h1);
    t2 = (uint32_t)__bfloat16_as_ushort(h2);
    t3 = (uint32_t)__bfloat16_as_ushort(h3);
}
__device__ __forceinline__ __nv_bfloat16 asbf(uint32_t t){
    return __ushort_as_bfloat16((unsigned short)t);
}

// ---------------- pre-split kernels -----------------------------------------
__global__ void __launch_bounds__(256) split_mat(
    const float* __restrict__ X,
    __nv_bfloat16* __restrict__ o1, __nv_bfloat16* __restrict__ o2,
    __nv_bfloat16* __restrict__ o3, int n4)
{
    int i = blockIdx.x*256 + threadIdx.x;
    if (i >= n4) return;
    float4 v = *(const float4*)&X[(size_t)i*4];
    uint32_t x1,x2,x3, y1,y2,y3, z1,z2,z3, u1,u2,u3;
    split3(v.x, x1,x2,x3); split3(v.y, y1,y2,y3);
    split3(v.z, z1,z2,z3); split3(v.w, u1,u2,u3);
    *(uint2*)&o1[(size_t)i*4] = make_uint2(x1|(y1<<16), z1|(u1<<16));
    *(uint2*)&o2[(size_t)i*4] = make_uint2(x2|(y2<<16), z2|(u2<<16));
    *(uint2*)&o3[(size_t)i*4] = make_uint2(x3|(y3<<16), z3|(u3<<16));
}

__global__ void __launch_bounds__(256) split_weights(
    const float* __restrict__ in_w, const float* __restrict__ out_w,
    const float* __restrict__ w1)
{
    int i = blockIdx.x*256 + threadIdx.x;     // float4 index, 2560*128 total
    if (i >= WROWS*128) return;
    int row = i >> 7;
    const float* src; int off;
    if (row < 1536){ src = in_w;  off = i; }
    else if (row < 2048){ src = out_w; off = i - 1536*128; }
    else { src = w1; off = i - 2048*128; }
    float4 v = ((const float4*)src)[off];
    uint32_t x1,x2,x3, y1,y2,y3, z1,z2,z3, u1,u2,u3;
    split3(v.x, x1,x2,x3); split3(v.y, y1,y2,y3);
    split3(v.z, z1,z2,z3); split3(v.w, u1,u2,u3);
    *(uint2*)&g_W1[(size_t)i*4] = make_uint2(x1|(y1<<16), z1|(u1<<16));
    *(uint2*)&g_W2[(size_t)i*4] = make_uint2(x2|(y2<<16), z2|(u2<<16));
    *(uint2*)&g_W3[(size_t)i*4] = make_uint2(x3|(y3<<16), z3|(u3<<16));
}

// ---------------- pure-bf16 tensor-core GEMM, 4-stage cp.async ring ---------
#define TILE_A   4096
#define TILE_W   8192
#define STAGE_B  (3*TILE_A + 3*TILE_W)   /* 36864 */
#define NSTAGE   4
#define GSM_SIZE (NSTAGE*STAGE_B)        /* 147456 */

template<bool RES, bool SPLITOUT>
__global__ void __launch_bounds__(256) gemm_bf(
    const __nv_bfloat16* __restrict__ A1, const __nv_bfloat16* __restrict__ A2,
    const __nv_bfloat16* __restrict__ A3,
    const __nv_bfloat16* __restrict__ W1, const __nv_bfloat16* __restrict__ W2,
    const __nv_bfloat16* __restrict__ W3,
    const float* __restrict__ bias, const float* __restrict__ res,
    float* __restrict__ C, int R, int K, int O)
{
    extern __shared__ __align__(128) char smem[];
    const uint32_t sb = smem_u32(smem);
    const int tid = threadIdx.x, lane = tid & 31, wid = tid >> 5;
    const int rb = blockIdx.y * 64, ob = blockIdx.x * 128;
    const int wm = wid & 1, wn = wid >> 1;

    float acc[2][4][4];
#pragma unroll
    for (int i=0;i<2;i++)
#pragma unroll
        for (int j=0;j<4;j++)
#pragma unroll
            for (int q=0;q<4;q++) acc[i][j][q]=0.f;

    const __nv_bfloat16* As[3] = {A1, A2, A3};
    const __nv_bfloat16* Ws[3] = {W1, W2, W3};

    const int ar = tid >> 2, aq = tid & 3;
    int gra = rb + ar; if (gra >= R) gra = R - 1;
    uint32_t aoffsw = (uint32_t)(ar*64 + aq*16); aoffsw ^= (aoffsw>>3) & 0x30u;

    auto issue_chunk = [&](int c){
        const uint32_t base = sb + (uint32_t)(c & (NSTAGE-1))*STAGE_B;
        const int k0 = c*32;
#pragma unroll
        for (int t = 0; t < 3; t++)
            cp16(base + t*TILE_A + aoffsw, As[t] + (size_t)gra*K + k0 + aq*8);
#pragma unroll
        for (int j = 0; j < 6; j++){
            int wi = j >> 1;
            int r  = (j & 1)*64 + (tid >> 2);
            int q  = tid & 3;
            uint32_t off = (uint32_t)(r*64 + q*16); off ^= (off>>3) & 0x30u;
            cp16(base + 3*TILE_A + wi*TILE_W + off, Ws[wi] + (size_t)(ob + r)*K + k0 + q*8);
        }
        asm volatile("cp.async.commit_group;" ::: "memory");
    };

    const int NTc = K / 32;
    issue_chunk(0);
    if (1 < NTc) issue_chunk(1);
    if (2 < NTc) issue_chunk(2);

    for (int c = 0; c < NTc; c++){
        const int inflight = NTc - 1 - c;
        if (inflight >= 2)      asm volatile("cp.async.wait_group 2;" ::: "memory");
        else if (inflight == 1) asm volatile("cp.async.wait_group 1;" ::: "memory");
        else                    asm volatile("cp.async.wait_group 0;" ::: "memory");
        __syncthreads();
        if (c+3 < NTc) issue_chunk(c+3);

        const uint32_t stg = sb + (uint32_t)(c & (NSTAGE-1))*STAGE_B;
#pragma unroll
        for (int ks = 0; ks < 2; ks++){
            uint32_t afr[3][2][4];
#pragma unroll
            for (int ai = 0; ai < 3; ai++)
#pragma unroll
                for (int mt = 0; mt < 2; mt++){
                    uint32_t row = (uint32_t)(wm*32 + mt*16 + (lane & 15));
                    uint32_t off = row*64 + (uint32_t)(ks*32) + (uint32_t)((lane >> 4) << 4);
                    off ^= (off >> 3) & 0x30u;
                    ldm4(afr[ai][mt], stg + ai*TILE_A + off);
                }
            uint32_t bfr[3][4][2];
#pragma unroll
            for (int wj = 0; wj < 3; wj++)
#pragma unroll
                for (int nt2 = 0; nt2 < 2; nt2++){
                    uint32_t row = (uint32_t)(wn*32 + nt2*16 + ((lane >> 4) << 3) + (lane & 7));
                    uint32_t off = row*64 + (uint32_t)(ks*32) + (uint32_t)(((lane >> 3) & 1) << 4);
                    off ^= (off >> 3) & 0x30u;
                    uint32_t r4[4];
                    ldm4(r4, stg + 3*TILE_A + wj*TILE_W + off);
                    bfr[wj][nt2*2][0]=r4[0];   bfr[wj][nt2*2][1]=r4[1];
                    bfr[wj][nt2*2+1][0]=r4[2]; bfr[wj][nt2*2+1][1]=r4[3];
                }
            const int PA[6] = {0,0,0,1,1,2};
            const int PW[6] = {0,1,2,0,1,0};
#pragma unroll
            for (int p = 0; p < 6; p++)
#pragma unroll
                for (int mt = 0; mt < 2; mt++)
#pragma unroll
                    for (int nt = 0; nt < 4; nt++)
                        mma16816(acc[mt][nt], afr[PA[p]][mt], bfr[PW[p]][nt]);
        }
    }
    __syncthreads();

    // ---- epilogue ----
    float* Cs = (float*)smem;
    {
        const int r0 = wm*32 + (lane >> 2);
        const int c0 = wn*32 + 2*(lane & 3);
#pragma unroll
        for (int mt = 0; mt < 2; mt++)
#pragma unroll
            for (int nt = 0; nt < 4; nt++){
                int row = r0 + mt*16, col = c0 + nt*8;
                Cs[row*129 + col]       = acc[mt][nt][0];
                Cs[row*129 + col + 1]   = acc[mt][nt][1];
                Cs[(row+8)*129 + col]   = acc[mt][nt][2];
                Cs[(row+8)*129 + col+1] = acc[mt][nt][3];
            }
    }
    __syncthreads();

    for (int idx = tid; idx < 64*128; idx += 256){
        int row = idx >> 7, c = idx & 127;
        int r = rb + row;
        if (r < R){
            float v = Cs[row*129 + c] + bias[ob + c];
            size_t g = (size_t)r*O + ob + c;
            if (RES) v += res[g];
            if (SPLITOUT){
                uint32_t t1,t2,t3;
                split3(v, t1,t2,t3);
                g_B1[g] = asbf(t1); g_B2[g] = asbf(t2); g_B3[g] = asbf(t3);
            } else {
                C[g] = v;
            }
        }
    }
}

// ---------------- attention: cp.async double-buffered K/V ------------------
#define ASM_Q   0
#define ASM_K0  1904
#define ASM_K1  5236
#define ASM_V0  8568
#define ASM_V1  11900
#define ASM_S   15232
#define ASM_FLOATS 16688   /* x4 = 66752 bytes */

__global__ void __launch_bounds__(256) attn_kernel()
{
    extern __shared__ __align__(16) float asmem[];
    const int qc = blockIdx.x, h = blockIdx.y, b = blockIdx.z;
    const int r0 = qc*28;
    const int tid = threadIdx.x, lane = tid & 31, w = tid >> 5;

    float* Qs = asmem + ASM_Q;
    float* S  = asmem + ASM_S;
    const uint32_t kbu[2] = {smem_u32(asmem + ASM_K0), smem_u32(asmem + ASM_K1)};
    const uint32_t vbu[2] = {smem_u32(asmem + ASM_V0), smem_u32(asmem + ASM_V1)};

    auto issue = [&](int t){
        const int buf = t & 1;
        for (int idx = tid; idx < 784; idx += 256){
            int j = idx >> 4, seg = idx & 15;
            size_t gb = (size_t)(b*NN + t*49 + j)*1536 + h*64 + seg*4;
            cp16(kbu[buf] + j*272 + seg*16, g_qkv + gb + 512);
            cp16(vbu[buf] + j*272 + seg*16, g_qkv + gb + 1024);
        }
        asm volatile("cp.async.commit_group;" ::: "memory");
    };

    issue(0);
    for (int idx=tid; idx<28*64; idx+=256){
        int row = idx>>6, kx = idx&63;
        Qs[row*68+kx] = g_qkv[(size_t)(b*NN + r0+row)*1536 + h*64 + kx];
    }

    const int nrows = (w<4)?4:3;
    float mrun[4], lrun[4], o0[4], o1[4];
#pragma unroll
    for (int rr=0; rr<4; rr++){ mrun[rr]=-1e30f; lrun[rr]=0.f; o0[rr]=0.f; o1[rr]=0.f; }

    const int srow = tid >> 3, jg = tid & 7;

    for (int t=0;t<4;t++){
        __syncthreads();
        if (t<3){
            issue(t+1);
            asm volatile("cp.async.wait_group 1;" ::: "memory");
        } else {
            asm volatile("cp.async.wait_group 0;" ::: "memory");
        }
        __syncthreads();

        const int buf = t & 1;
        const float* Ks = asmem + (buf ? ASM_K1 : ASM_K0);
        const float* Vs = asmem + (buf ? ASM_V1 : ASM_V0);

        if (srow < 28){
            float acc[7];
#pragma unroll
            for (int jj=0;jj<7;jj++) acc[jj]=0.f;
            const float4* q4 = (const float4*)&Qs[srow*68];
#pragma unroll
            for (int kx=0; kx<16; kx++){
                float4 qa = q4[kx];
#pragma unroll
                for (int jj=0;jj<7;jj++){
                    int j = jg + 8*jj;
                    if (j < 49){
                        float4 ka = *(const float4*)&Ks[j*68 + kx*4];
                        acc[jj] += qa.x*ka.x + qa.y*ka.y + qa.z*ka.z + qa.w*ka.w;
                    }
                }
            }
#pragma unroll
            for (int jj=0;jj<7;jj++){
                int j = jg + 8*jj;
                if (j < 49) S[srow*52+j] = acc[jj]*0.125f;
            }
        }
        __syncthreads();

#pragma unroll
        for (int rr=0; rr<4; rr++){
            if (rr >= nrows) break;
            int row = w + 8*rr;
            float s0 = (lane<49) ? S[row*52+lane]    : -1e30f;
            float s1 = (lane<17) ? S[row*52+lane+32] : -1e30f;
            float tm = warp_max(fmaxf(s0,s1));
            float mnew = fmaxf(mrun[rr], tm);
            float alpha = __expf(mrun[rr]-mnew);
            float p0 = (lane<49) ? __expf(s0-mnew) : 0.f;
            float p1 = (lane<17) ? __expf(s1-mnew) : 0.f;
            float psum = warp_sum(p0+p1);
            lrun[rr] = lrun[rr]*alpha + psum;
            mrun[rr] = mnew;
            if (lane<49) S[row*52+lane]    = p0;
            if (lane<17) S[row*52+lane+32] = p1;
            o0[rr]*=alpha; o1[rr]*=alpha;
        }
        __syncwarp();

        // AV: j unrolled by 4; S read as float4 (row*52 is 16B aligned)
#pragma unroll 3
        for (int j4=0; j4<12; j4++){
            const int jb = j4*4;
            float va0 = Vs[(jb+0)*68+lane], wa0 = Vs[(jb+0)*68+lane+32];
            float va1 = Vs[(jb+1)*68+lane], wa1 = Vs[(jb+1)*68+lane+32];
            float va2 = Vs[(jb+2)*68+lane], wa2 = Vs[(jb+2)*68+lane+32];
            float va3 = Vs[(jb+3)*68+lane], wa3 = Vs[(jb+3)*68+lane+32];
#pragma unroll
            for (int rr=0; rr<4; rr++){
                if (rr >= nrows) break;
                float4 p = *(const float4*)&S[(w + 8*rr)*52 + jb];
                o0[rr] += p.x*va0 + p.y*va1 + p.z*va2 + p.w*va3;
                o1[rr] += p.x*wa0 + p.y*wa1 + p.z*wa2 + p.w*wa3;
            }
        }
        {   // remainder j = 48
            float v0 = Vs[48*68+lane];
            float v1 = Vs[48*68+lane+32];
#pragma unroll
            for (int rr=0; rr<4; rr++){
                if (rr >= nrows) break;
                float pj = S[(w + 8*rr)*52 + 48];
                o0[rr] += pj * v0;
                o1[rr] += pj * v1;
            }
        }
    }
    for (int rr=0; rr<nrows; rr++){
        int row = w + 8*rr;
        float inv = 1.f/lrun[rr];
        size_t base = (size_t)(b*NN + r0+row)*512 + h*64;
        uint32_t t1,t2,t3;
        split3(o0[rr]*inv, t1,t2,t3);
        g_A1[base+lane] = asbf(t1); g_A2[base+lane] = asbf(t2); g_A3[base+lane] = asbf(t3);
        split3(o1[rr]*inv, t1,t2,t3);
        g_A1[base+lane+32] = asbf(t1); g_A2[base+lane+32] = asbf(t2); g_A3[base+lane+32] = asbf(t3);
    }
}

// ---------------- fused LN + GELU + w2 + decompose --------------------------
__global__ void __launch_bounds__(256) ln_decomp(
    const float* __restrict__ hin, const float* __restrict__ lng,
    const float* __restrict__ lnb, const float* __restrict__ w2,
    const float* __restrict__ b2,
    const float* __restrict__ F, const float* __restrict__ tpl,
    const int* __restrict__ kptr, float* __restrict__ out)
{
    const int r = blockIdx.x, tid = threadIdx.x, lane = tid&31, w = tid>>5;
    __shared__ float fs[512];
    __shared__ float gs[512];
    __shared__ float red[16];
    __shared__ int hist[8][256];
    __shared__ unsigned int thr_s[MM];
    __shared__ float scale_s[MM];
    __shared__ unsigned int eqmask_s[MM][16];

    float x0 = hin[(size_t)r*512 + tid];
    float x1 = hin[(size_t)r*512 + tid + 256];
    fs[tid]     = F[(size_t)r*512 + tid];
    fs[tid+256] = F[(size_t)r*512 + tid + 256];

    float s  = warp_sum(x0 + x1);
    float sq = warp_sum(x0*x0 + x1*x1);
    if (lane==0){ red[w]=s; red[w+8]=sq; }
    __syncthreads();
    if (tid==0){
        float S=0,Q=0;
#pragma unroll
        for (int i=0;i<8;i++){ S+=red[i]; Q+=red[i+8]; }
        red[0]=S; red[1]=Q;
    }
    __syncthreads();
    float mean = red[0]*(1.f/512.f);
    float var  = red[1]*(1.f/512.f) - mean*mean;
    float rstd = rsqrtf(var + 1e-5f);
    {
        float y0 = (x0-mean)*rstd*lng[tid]     + lnb[tid];
        float y1 = (x1-mean)*rstd*lng[tid+256] + lnb[tid+256];
        gs[tid]     = 0.5f*y0*(1.f+erff(y0*0.70710678118654752f));
        gs[tid+256] = 0.5f*y1*(1.f+erff(y1*0.70710678118654752f));
    }
    __syncthreads();

    const int kval = *kptr;   // 51
    const int nm = (w<4) ? 3 : 2;
    float qpv[3];
    for (int i=0; i<nm; i++){
        int m = w + 8*i;
        float acc = 0.f;
#pragma unroll
        for (int j=0;j<16;j++){
            int d = lane + 32*j;
            acc += gs[d]*w2[m*512+d];
        }
        qpv[i] = warp_sum(acc) + b2[m];
    }

    for (int i=0; i<nm; i++){
        int m = w + 8*i;
        float p[16]; unsigned int u[16];
#pragma unroll
        for (int j=0;j<16;j++){
            int d = lane + 32*j;
            p[j] = fs[d]*tpl[m*512+d];
            u[j] = __float_as_uint(fabsf(p[j]));
        }
        unsigned int pref=0u, pmask=0u; int kk = kval;
        const int shifts[4]  = {23,15,7,0};
        const unsigned int dmasks[4] = {0xFFu,0xFFu,0xFFu,0x7Fu};
#pragma unroll
        for (int ps=0; ps<4; ps++){
            const int sh = shifts[ps]; const unsigned int dm = dmasks[ps];
            for (int bI=lane; bI<256; bI+=32) hist[w][bI]=0;
            __syncwarp();
#pragma unroll
            for (int j=0;j<16;j++){
                if ((u[j] & pmask) == pref)
                    atomicAdd(&hist[w][(u[j]>>sh)&dm], 1);
            }
            __syncwarp();
            int base = 255 - 8*lane;
            int s8 = 0;
#pragma unroll
            for (int j=0;j<8;j++) s8 += hist[w][base-j];
            int incl = s8;
#pragma unroll
            for (int off=1; off<32; off<<=1){
                int v = __shfl_up_sync(0xffffffffu, incl, off);
                if (lane>=off) incl += v;
            }
            int excl = incl - s8;
            int dig = -1, kk2 = 0;
            if (excl < kk && incl >= kk){
                int run = excl;
#pragma unroll
                for (int j=0;j<8;j++){
                    int hc = hist[w][base-j];
                    if (dig<0 && run+hc >= kk){ dig = base-j; kk2 = kk-run; }
                    run += hc;
                }
            }
            unsigned int bal = __ballot_sync(0xffffffffu, dig>=0);
            int src = __ffs(bal)-1;
            dig = __shfl_sync(0xffffffffu, dig, src);
            kk  = __shfl_sync(0xffffffffu, kk2, src);
            pref  |= ((unsigned int)dig) << sh;
            pmask |= dm << sh;
            __syncwarp();
        }
        const unsigned int thr = pref;
        const int needeq = kk;

        if (lane<16) eqmask_s[m][lane]=0u;
        __syncwarp();
        float ss = 0.f; int eqbase = 0;
#pragma unroll
        for (int j=0;j<16;j++){
            bool eq = (u[j]==thr);
            unsigned int eb = __ballot_sync(0xffffffffu, eq);
            bool esel = eq && (eqbase + __popc(eb & ((1u<<lane)-1u)) < needeq);
            eqbase += __popc(eb);
            unsigned int sb2 = __ballot_sync(0xffffffffu, esel);
            if (lane==0) eqmask_s[m][j] = sb2;
            if (u[j] > thr || esel) ss += p[j]*p[j];
        }
        ss = warp_sum(ss);
        if (lane==0){
            float q = qpv[i];
            float nrm = fabsf(q)*sqrtf(ss);
            scale_s[m] = q / fmaxf(nrm, 1e-6f);
            thr_s[m]   = thr;
        }
    }
    __syncthreads();

    const size_t obase = (size_t)r * (512*MM);
    for (int base = tid*4; base < 512*MM; base += 1024){
        float4 vv;
        float* pv4 = (float*)&vv;
#pragma unroll
        for (int e=0;e<4;e++){
            int lin = base + e;
            int d = lin / MM, m = lin - d*MM;
            float pv = fs[d]*tpl[m*512+d];
            unsigned int uu = __float_as_uint(fabsf(pv));
            unsigned int thr = thr_s[m];
            bool sel = (uu > thr) ||
                       (uu == thr && ((eqmask_s[m][d>>5] >> (d&31)) & 1u));
            pv4[e] = sel ? pv*scale_s[m] : 0.f;
        }
        *(float4*)&out[obase + base] = vv;
    }
}

// ---------------- launch ----------------
extern "C" void kernel_launch(void* const* d_in, const int* in_sizes, int n_in,
                              void* d_out, int out_size)
{
    (void)in_sizes; (void)n_in; (void)out_size;
    const float* F     = (const float*)d_in[0];
    const float* in_w  = (const float*)d_in[1];
    const float* in_b  = (const float*)d_in[2];
    const float* out_w = (const float*)d_in[3];
    const float* out_b = (const float*)d_in[4];
    const float* w1    = (const float*)d_in[5];
    const float* b1    = (const float*)d_in[6];
    const float* ln_g  = (const float*)d_in[7];
    const float* ln_b  = (const float*)d_in[8];
    const float* w2    = (const float*)d_in[9];
    const float* b2    = (const float*)d_in[10];
    const float* tpl   = (const float*)d_in[11];
    const int*   kptr  = (const int*)d_in[12];
    float* out = (float*)d_out;

    void *p_qkv, *p_h;
    void *pA1, *pA2, *pA3, *pB1, *pB2, *pB3, *pW1, *pW2, *pW3;
    cudaGetSymbolAddress(&p_qkv, g_qkv);
    cudaGetSymbolAddress(&p_h,   g_h);
    cudaGetSymbolAddress(&pA1, g_A1); cudaGetSymbolAddress(&pA2, g_A2);
    cudaGetSymbolAddress(&pA3, g_A3);
    cudaGetSymbolAddress(&pB1, g_B1); cudaGetSymbolAddress(&pB2, g_B2);
    cudaGetSymbolAddress(&pB3, g_B3);
    cudaGetSymbolAddress(&pW1, g_W1); cudaGetSymbolAddress(&pW2, g_W2);
    cudaGetSymbolAddress(&pW3, g_W3);
    float* qkv = (float*)p_qkv;
    float* hb  = (float*)p_h;
    __nv_bfloat16 *A1=(__nv_bfloat16*)pA1, *A2=(__nv_bfloat16*)pA2, *A3=(__nv_bfloat16*)pA3;
    __nv_bfloat16 *B1=(__nv_bfloat16*)pB1, *B2=(__nv_bfloat16*)pB2, *B3=(__nv_bfloat16*)pB3;
    __nv_bfloat16 *W1=(__nv_bfloat16*)pW1, *W2=(__nv_bfloat16*)pW2, *W3=(__nv_bfloat16*)pW3;

    cudaFuncSetAttribute((const void*)gemm_bf<false,false>,
                         cudaFuncAttributeMaxDynamicSharedMemorySize, GSM_SIZE);
    cudaFuncSetAttribute((const void*)gemm_bf<true,true>,
                         cudaFuncAttributeMaxDynamicSharedMemorySize, GSM_SIZE);
    cudaFuncSetAttribute((const void*)attn_kernel,
                         cudaFuncAttributeMaxDynamicSharedMemorySize, ASM_FLOATS*4);

    const int gy = (RTOT + 63) / 64;   // 49
    const int nA4 = RTOT*DD/4;

    split_weights<<<(WROWS*128 + 255)/256, 256>>>(in_w, out_w, w1);
    split_mat<<<(nA4 + 255)/256, 256>>>(F, A1, A2, A3, nA4);
    gemm_bf<false,false><<<dim3(12, gy), 256, GSM_SIZE>>>(A1, A2, A3, W1, W2, W3,
                                                          in_b, nullptr, qkv, RTOT, DD, 1536);
    attn_kernel<<<dim3(7, HH, BB), 256, ASM_FLOATS*4>>>();
    gemm_bf<true,true><<<dim3(4, gy), 256, GSM_SIZE>>>(A1, A2, A3,
        W1+1536*DD, W2+1536*DD, W3+1536*DD, out_b, F, hb, RTOT, DD, 512);
    gemm_bf<false,false><<<dim3(4, gy), 256, GSM_SIZE>>>(B1, B2, B3,
        W1+2048*DD, W2+2048*DD, W3+2048*DD, b1, nullptr, hb, RTOT, DD, 512);
    ln_decomp<<<RTOT, 256>>>(hb, ln_g, ln_b, w2, b2, F, tpl, kptr, out);
}